// round 1
// baseline (speedup 1.0000x reference)
#include <cuda_runtime.h>
#include <cuda_bf16.h>
#include <math.h>

// Problem constants (fixed shapes)
#define B_   16
#define C_   384
#define C3   1152
#define H_   64
#define W_   64
#define HW   4096
#define NH   8
#define DH   48          // C_/NH
#define EPSN 1e-12f

// Scratch: qkv buffer (after 1x1 conv, then dwconv in-place, then attention
// output written in-place into the q region).
__device__ float g_qkv[(size_t)B_ * C3 * HW];          // 302 MB
__device__ float g_inv[(size_t)B_ * 2 * C_];           // inv-norms for q,k rows

// ---------------------------------------------------------------------------
// SGEMM: C[b] = A @ B[b], A is MxK row-major (weights, shared over batch),
// B is KxN row-major, C is MxN row-major. 128x128x8 tile, 256 threads, 8x8/thr.
// M,N,K all divisible by tile sizes here (1152/384, 4096, 384).
// ---------------------------------------------------------------------------
__global__ __launch_bounds__(256, 2)
void sgemm128(const float* __restrict__ A, const float* __restrict__ Bg,
              float* __restrict__ Cg, int M, int N, int K,
              size_t strideB, size_t strideC)
{
    const float* Bp = Bg + (size_t)blockIdx.z * strideB;
    float*       Cp = Cg + (size_t)blockIdx.z * strideC;

    const int m0 = blockIdx.y * 128;
    const int n0 = blockIdx.x * 128;

    __shared__ float As[8][128];
    __shared__ float Bs[8][128];

    const int t  = threadIdx.x;
    const int tx = t & 15;        // 0..15
    const int ty = t >> 4;        // 0..15

    float acc[8][8];
#pragma unroll
    for (int i = 0; i < 8; i++)
#pragma unroll
        for (int j = 0; j < 8; j++) acc[i][j] = 0.f;

    for (int k0 = 0; k0 < K; k0 += 8) {
        // Load A tile (128 rows x 8 cols), store transposed
        {
            const int row = t >> 1;          // 0..127
            const int col = (t & 1) * 4;     // 0 or 4
            float4 a = *(const float4*)&A[(size_t)(m0 + row) * K + k0 + col];
            As[col + 0][row] = a.x;
            As[col + 1][row] = a.y;
            As[col + 2][row] = a.z;
            As[col + 3][row] = a.w;
        }
        // Load B tile (8 rows x 128 cols)
        {
            const int row = t >> 5;          // 0..7
            const int col = (t & 31) * 4;    // 0..124
            *(float4*)&Bs[row][col] =
                *(const float4*)&Bp[(size_t)(k0 + row) * N + n0 + col];
        }
        __syncthreads();

#pragma unroll
        for (int kk = 0; kk < 8; kk++) {
            float a[8], b[8];
#pragma unroll
            for (int i = 0; i < 4; i++) {
                ((float4*)a)[0] = *(float4*)&As[kk][ty * 8];
                ((float4*)a)[1] = *(float4*)&As[kk][ty * 8 + 4];
                ((float4*)b)[0] = *(float4*)&Bs[kk][tx * 8];
                ((float4*)b)[1] = *(float4*)&Bs[kk][tx * 8 + 4];
                break;
            }
#pragma unroll
            for (int i = 0; i < 8; i++)
#pragma unroll
                for (int j = 0; j < 8; j++)
                    acc[i][j] = fmaf(a[i], b[j], acc[i][j]);
        }
        __syncthreads();
    }

#pragma unroll
    for (int i = 0; i < 8; i++) {
        float4 v0 = make_float4(acc[i][0], acc[i][1], acc[i][2], acc[i][3]);
        float4 v1 = make_float4(acc[i][4], acc[i][5], acc[i][6], acc[i][7]);
        float* crow = &Cp[(size_t)(m0 + ty * 8 + i) * N + n0 + tx * 8];
        *(float4*)(crow)     = v0;
        *(float4*)(crow + 4) = v1;
    }
}

// ---------------------------------------------------------------------------
// Depthwise 3x3 SAME conv, in place. One block per (b, channel) plane.
// Full 64x64 plane + zero halo kept in smem, so in-place write is safe.
// ---------------------------------------------------------------------------
__global__ __launch_bounds__(256)
void dwconv3x3(float* __restrict__ qkv, const float* __restrict__ wdw)
{
    const int plane = blockIdx.x;            // b*1152 + ch
    const int ch    = plane % C3;
    float* p = qkv + (size_t)plane * HW;

    __shared__ float s[66][66];
    const int t = threadIdx.x;

    for (int i = t; i < 66 * 66; i += 256) ((float*)s)[i] = 0.f;
    __syncthreads();
    for (int i = t; i < HW; i += 256) {
        int y = i >> 6, x = i & 63;
        s[y + 1][x + 1] = p[i];
    }

    float w[9];
#pragma unroll
    for (int j = 0; j < 9; j++) w[j] = wdw[ch * 9 + j];
    __syncthreads();

    for (int i = t; i < HW; i += 256) {
        int y = i >> 6, x = i & 63;
        float acc = 0.f;
#pragma unroll
        for (int dy = 0; dy < 3; dy++)
#pragma unroll
            for (int dx = 0; dx < 3; dx++)
                acc = fmaf(s[y + dy][x + dx], w[dy * 3 + dx], acc);
        p[i] = acc;
    }
}

// ---------------------------------------------------------------------------
// Row inverse L2 norms for q and k channels (first 2*C_ channels of qkv).
// One block per (b, ch<768) row of 4096 elements.
// ---------------------------------------------------------------------------
__global__ __launch_bounds__(256)
void rownorm(const float* __restrict__ qkv, float* __restrict__ inv)
{
    const int r  = blockIdx.x;               // b*768 + ch
    const int b  = r / (2 * C_);
    const int ch = r % (2 * C_);
    const float* p = qkv + ((size_t)b * C3 + ch) * HW;

    float s = 0.f;
    for (int i = threadIdx.x; i < HW; i += 256) {
        float v = p[i];
        s = fmaf(v, v, s);
    }
    // warp + smem reduction
    for (int off = 16; off > 0; off >>= 1)
        s += __shfl_down_sync(0xffffffffu, s, off);
    __shared__ float red[8];
    if ((threadIdx.x & 31) == 0) red[threadIdx.x >> 5] = s;
    __syncthreads();
    if (threadIdx.x == 0) {
        float tot = 0.f;
        for (int i = 0; i < 8; i++) tot += red[i];
        inv[r] = 1.f / fmaxf(sqrtf(tot), EPSN);
    }
}

// ---------------------------------------------------------------------------
// Channel attention per (b, head): S = (Qn Kn^T)*temp, softmax rows,
// O = S_soft @ V written in place over the q-channel region.
// 256 threads. Phase1: 3x3 register blocking; Phase3: 3x4.
// ---------------------------------------------------------------------------
__global__ __launch_bounds__(256)
void attn_kernel(float* __restrict__ qkv, const float* __restrict__ inv,
                 const float* __restrict__ temp)
{
    const int bh = blockIdx.x;
    const int b  = bh >> 3;
    const int h  = bh & 7;
    const int t  = threadIdx.x;
    const int tx = t & 15;
    const int ty = t >> 4;

    __shared__ float Qs[DH][65];     // aliased as V tile in phase 3
    __shared__ float Ks[DH][65];
    __shared__ float S [DH][48];

    float* qbase = qkv + ((size_t)b * C3 + h * DH) * HW;
    float* kbase = qbase + (size_t)C_ * HW;
    float* vbase = qbase + (size_t)2 * C_ * HW;
    const float* invq = inv + b * 2 * C_ + h * DH;
    const float* invk = invq + C_;

    // ---- Phase 1: S = Qn @ Kn^T ----
    float acc[3][3];
#pragma unroll
    for (int i = 0; i < 3; i++)
#pragma unroll
        for (int j = 0; j < 3; j++) acc[i][j] = 0.f;

    for (int k0 = 0; k0 < HW; k0 += 64) {
        for (int i = t; i < DH * 64; i += 256) {
            int r = i >> 6, c = i & 63;
            Qs[r][c] = qbase[(size_t)r * HW + k0 + c] * invq[r];
            Ks[r][c] = kbase[(size_t)r * HW + k0 + c] * invk[r];
        }
        __syncthreads();
#pragma unroll 8
        for (int kk = 0; kk < 64; kk++) {
            float q0 = Qs[ty * 3 + 0][kk];
            float q1 = Qs[ty * 3 + 1][kk];
            float q2 = Qs[ty * 3 + 2][kk];
            float b0 = Ks[tx * 3 + 0][kk];
            float b1 = Ks[tx * 3 + 1][kk];
            float b2 = Ks[tx * 3 + 2][kk];
            acc[0][0] = fmaf(q0, b0, acc[0][0]);
            acc[0][1] = fmaf(q0, b1, acc[0][1]);
            acc[0][2] = fmaf(q0, b2, acc[0][2]);
            acc[1][0] = fmaf(q1, b0, acc[1][0]);
            acc[1][1] = fmaf(q1, b1, acc[1][1]);
            acc[1][2] = fmaf(q1, b2, acc[1][2]);
            acc[2][0] = fmaf(q2, b0, acc[2][0]);
            acc[2][1] = fmaf(q2, b1, acc[2][1]);
            acc[2][2] = fmaf(q2, b2, acc[2][2]);
        }
        __syncthreads();
    }

    const float tv = temp[h];
#pragma unroll
    for (int i = 0; i < 3; i++)
#pragma unroll
        for (int j = 0; j < 3; j++)
            S[ty * 3 + i][tx * 3 + j] = acc[i][j] * tv;
    __syncthreads();

    // ---- Phase 2: row softmax (48 rows, one thread each) ----
    if (t < DH) {
        float m = -INFINITY;
#pragma unroll
        for (int e = 0; e < 48; e++) m = fmaxf(m, S[t][e]);
        float sum = 0.f;
#pragma unroll
        for (int e = 0; e < 48; e++) {
            float ex = expf(S[t][e] - m);
            S[t][e] = ex;
            sum += ex;
        }
        float is = 1.f / sum;
#pragma unroll
        for (int e = 0; e < 48; e++) S[t][e] *= is;
    }
    __syncthreads();

    // ---- Phase 3: O = S_soft @ V, written over q region ----
    for (int n0 = 0; n0 < HW; n0 += 64) {
        for (int i = t; i < DH * 64; i += 256) {
            int r = i >> 6, c = i & 63;
            Qs[r][c] = vbase[(size_t)r * HW + n0 + c];   // V tile
        }
        __syncthreads();

        float o[3][4];
#pragma unroll
        for (int i = 0; i < 3; i++)
#pragma unroll
            for (int j = 0; j < 4; j++) o[i][j] = 0.f;

#pragma unroll 8
        for (int e = 0; e < 48; e++) {
            float a0 = S[ty * 3 + 0][e];
            float a1 = S[ty * 3 + 1][e];
            float a2 = S[ty * 3 + 2][e];
            float v0 = Qs[e][tx * 4 + 0];
            float v1 = Qs[e][tx * 4 + 1];
            float v2 = Qs[e][tx * 4 + 2];
            float v3 = Qs[e][tx * 4 + 3];
            o[0][0] = fmaf(a0, v0, o[0][0]); o[0][1] = fmaf(a0, v1, o[0][1]);
            o[0][2] = fmaf(a0, v2, o[0][2]); o[0][3] = fmaf(a0, v3, o[0][3]);
            o[1][0] = fmaf(a1, v0, o[1][0]); o[1][1] = fmaf(a1, v1, o[1][1]);
            o[1][2] = fmaf(a1, v2, o[1][2]); o[1][3] = fmaf(a1, v3, o[1][3]);
            o[2][0] = fmaf(a2, v0, o[2][0]); o[2][1] = fmaf(a2, v1, o[2][1]);
            o[2][2] = fmaf(a2, v2, o[2][2]); o[2][3] = fmaf(a2, v3, o[2][3]);
        }

#pragma unroll
        for (int i = 0; i < 3; i++) {
            float4 v = make_float4(o[i][0], o[i][1], o[i][2], o[i][3]);
            *(float4*)&qbase[(size_t)(ty * 3 + i) * HW + n0 + tx * 4] = v;
        }
        __syncthreads();
    }
}

// ---------------------------------------------------------------------------
extern "C" void kernel_launch(void* const* d_in, const int* in_sizes, int n_in,
                              void* d_out, int out_size)
{
    const float* x      = (const float*)d_in[0];   // (16,384,64,64)
    const float* w_qkv  = (const float*)d_in[1];   // (1152,384)
    const float* w_dw   = (const float*)d_in[2];   // (1152,1,3,3)
    const float* w_proj = (const float*)d_in[3];   // (384,384)
    const float* temp   = (const float*)d_in[4];   // (1,8,1,1)
    float* out = (float*)d_out;                    // (16,384,64,64)

    float* qkv;
    float* inv;
    cudaGetSymbolAddress((void**)&qkv, g_qkv);
    cudaGetSymbolAddress((void**)&inv, g_inv);

    // 1) qkv = w_qkv @ x   (per batch: M=1152, K=384, N=4096)
    {
        dim3 grid(HW / 128, C3 / 128, B_);
        sgemm128<<<grid, 256>>>(w_qkv, x, qkv, C3, HW, C_,
                                (size_t)C_ * HW, (size_t)C3 * HW);
    }
    // 2) depthwise 3x3, in place
    dwconv3x3<<<B_ * C3, 256>>>(qkv, w_dw);
    // 3) inverse L2 norms for q,k rows
    rownorm<<<B_ * 2 * C_, 256>>>(qkv, inv);
    // 4) channel attention (writes into q region of qkv)
    attn_kernel<<<B_ * NH, 256>>>(qkv, inv, temp);
    // 5) out = w_proj @ attn_out  (per batch: M=384, K=384, N=4096)
    {
        dim3 grid(HW / 128, C_ / 128, B_);
        sgemm128<<<grid, 256>>>(w_proj, qkv, out, C_, HW, C_,
                                (size_t)C3 * HW, (size_t)C_ * HW);
    }
}

// round 2
// speedup vs baseline: 1.2500x; 1.2500x over previous
#include <cuda_runtime.h>
#include <cuda_bf16.h>
#include <math.h>

// Problem constants (fixed shapes)
#define B_   16
#define C_   384
#define C3   1152
#define HW   4096
#define NH   8
#define DH   48          // C_/NH
#define NCH  8           // split-K chunks for attention scores
#define CHUNK 512        // HW / NCH
#define EPSN 1e-12f

// Scratch buffers (allocation-guard-safe __device__ globals)
__device__ float g_qkv[(size_t)B_ * C3 * HW];              // 302 MB
__device__ float g_inv[B_ * 2 * C_];                       // q,k row inv-norms
__device__ float g_Spart[NCH][B_ * NH][DH * DH];           // 9.4 MB partial scores
__device__ float g_S[B_ * NH][DH * DH];                    // softmaxed scores

// ---------------------------------------------------------------------------
// SGEMM: C[b] = A @ B[b]. A MxK row-major (weights), B KxN, C MxN.
// 128x128x8 tiles, 256 threads, 8x8/thread, register-prefetch pipelining.
// ---------------------------------------------------------------------------
__global__ __launch_bounds__(256, 2)
void sgemm128(const float* __restrict__ A, const float* __restrict__ Bg,
              float* __restrict__ Cg, int M, int N, int K,
              size_t strideB, size_t strideC)
{
    const float* Bp = Bg + (size_t)blockIdx.z * strideB;
    float*       Cp = Cg + (size_t)blockIdx.z * strideC;

    const int m0 = blockIdx.y * 128;
    const int n0 = blockIdx.x * 128;

    __shared__ float As[8][128];
    __shared__ float Bs[8][128];

    const int t  = threadIdx.x;
    const int tx = t & 15;
    const int ty = t >> 4;

    const int arow = t >> 1;            // 0..127
    const int acol = (t & 1) * 4;       // 0 or 4
    const int brow = t >> 5;            // 0..7
    const int bcol = (t & 31) * 4;      // 0..124

    const float* Aptr = &A[(size_t)(m0 + arow) * K + acol];
    const float* Bptr = &Bp[(size_t)brow * N + n0 + bcol];

    float acc[8][8];
#pragma unroll
    for (int i = 0; i < 8; i++)
#pragma unroll
        for (int j = 0; j < 8; j++) acc[i][j] = 0.f;

    // prologue: load first k-tile into registers
    float4 aN = *(const float4*)Aptr;
    float4 bN = *(const float4*)Bptr;

    for (int k0 = 0; k0 < K; k0 += 8) {
        As[acol + 0][arow] = aN.x;
        As[acol + 1][arow] = aN.y;
        As[acol + 2][arow] = aN.z;
        As[acol + 3][arow] = aN.w;
        *(float4*)&Bs[brow][bcol] = bN;
        __syncthreads();

        if (k0 + 8 < K) {
            aN = *(const float4*)(Aptr + k0 + 8);
            bN = *(const float4*)(Bptr + (size_t)(k0 + 8) * N);
        }

#pragma unroll
        for (int kk = 0; kk < 8; kk++) {
            float a[8], b[8];
            *(float4*)&a[0] = *(float4*)&As[kk][ty * 8];
            *(float4*)&a[4] = *(float4*)&As[kk][ty * 8 + 4];
            *(float4*)&b[0] = *(float4*)&Bs[kk][tx * 8];
            *(float4*)&b[4] = *(float4*)&Bs[kk][tx * 8 + 4];
#pragma unroll
            for (int i = 0; i < 8; i++)
#pragma unroll
                for (int j = 0; j < 8; j++)
                    acc[i][j] = fmaf(a[i], b[j], acc[i][j]);
        }
        __syncthreads();
    }

#pragma unroll
    for (int i = 0; i < 8; i++) {
        float4 v0 = make_float4(acc[i][0], acc[i][1], acc[i][2], acc[i][3]);
        float4 v1 = make_float4(acc[i][4], acc[i][5], acc[i][6], acc[i][7]);
        float* crow = &Cp[(size_t)(m0 + ty * 8 + i) * N + n0 + tx * 8];
        *(float4*)(crow)     = v0;
        *(float4*)(crow + 4) = v1;
    }
}

// ---------------------------------------------------------------------------
// Depthwise 3x3 SAME conv, in place, with fused sum-of-squares -> inv norm
// for the q/k channels (ch < 768). One block per (b, channel) plane.
// ---------------------------------------------------------------------------
__global__ __launch_bounds__(256)
void dwconv3x3(float* __restrict__ qkv, const float* __restrict__ wdw,
               float* __restrict__ inv)
{
    const int plane = blockIdx.x;            // b*1152 + ch
    const int b     = plane / C3;
    const int ch    = plane % C3;
    float* p = qkv + (size_t)plane * HW;

    __shared__ float s[66][66];
    const int t = threadIdx.x;

    for (int i = t; i < 66 * 66; i += 256) ((float*)s)[i] = 0.f;
    __syncthreads();
    for (int i = t; i < HW; i += 256) {
        int y = i >> 6, x = i & 63;
        s[y + 1][x + 1] = p[i];
    }

    float w[9];
#pragma unroll
    for (int j = 0; j < 9; j++) w[j] = wdw[ch * 9 + j];
    __syncthreads();

    float ss = 0.f;
    for (int i = t; i < HW; i += 256) {
        int y = i >> 6, x = i & 63;
        float acc = 0.f;
#pragma unroll
        for (int dy = 0; dy < 3; dy++)
#pragma unroll
            for (int dx = 0; dx < 3; dx++)
                acc = fmaf(s[y + dy][x + dx], w[dy * 3 + dx], acc);
        p[i] = acc;
        ss = fmaf(acc, acc, ss);
    }

    if (ch < 2 * C_) {
        for (int off = 16; off > 0; off >>= 1)
            ss += __shfl_down_sync(0xffffffffu, ss, off);
        __shared__ float red[8];
        if ((t & 31) == 0) red[t >> 5] = ss;
        __syncthreads();
        if (t == 0) {
            float tot = 0.f;
#pragma unroll
            for (int i = 0; i < 8; i++) tot += red[i];
            inv[b * 2 * C_ + ch] = 1.f / fmaxf(sqrtf(tot), EPSN);
        }
    }
}

// ---------------------------------------------------------------------------
// Attention phase 1: partial S = Qn @ Kn^T over one k-chunk of 512.
// grid = (NCH, B_*NH), 256 threads, 3x3 per thread (rows ty+16i, cols tx+16j).
// ---------------------------------------------------------------------------
__global__ __launch_bounds__(256)
void attn_scores(const float* __restrict__ qkv, const float* __restrict__ inv)
{
    const int bh    = blockIdx.y;
    const int b     = bh >> 3;
    const int h     = bh & 7;
    const int chunk = blockIdx.x;
    const int t  = threadIdx.x;
    const int tx = t & 15;
    const int ty = t >> 4;

    const float* qbase = qkv + ((size_t)b * C3 + h * DH) * HW;
    const float* kbase = qbase + (size_t)C_ * HW;

    __shared__ float Qs[DH][65];
    __shared__ float Ks[DH][65];
    __shared__ float ivq[DH], ivk[DH];

    if (t < DH)            ivq[t] = inv[b * 2 * C_ + h * DH + t];
    else if (t < 2 * DH)   ivk[t - DH] = inv[b * 2 * C_ + C_ + h * DH + (t - DH)];
    __syncthreads();

    float acc[3][3];
#pragma unroll
    for (int i = 0; i < 3; i++)
#pragma unroll
        for (int j = 0; j < 3; j++) acc[i][j] = 0.f;

    const int kb = chunk * CHUNK;
    for (int k0 = 0; k0 < CHUNK; k0 += 64) {
        for (int i = t; i < DH * 16; i += 256) {
            int r  = i >> 4;
            int c4 = (i & 15) * 4;
            float4 qv = *(const float4*)&qbase[(size_t)r * HW + kb + k0 + c4];
            float4 kv = *(const float4*)&kbase[(size_t)r * HW + kb + k0 + c4];
            float sq = ivq[r], sk = ivk[r];
            Qs[r][c4 + 0] = qv.x * sq; Qs[r][c4 + 1] = qv.y * sq;
            Qs[r][c4 + 2] = qv.z * sq; Qs[r][c4 + 3] = qv.w * sq;
            Ks[r][c4 + 0] = kv.x * sk; Ks[r][c4 + 1] = kv.y * sk;
            Ks[r][c4 + 2] = kv.z * sk; Ks[r][c4 + 3] = kv.w * sk;
        }
        __syncthreads();

#pragma unroll 16
        for (int kk = 0; kk < 64; kk++) {
            float q0 = Qs[ty     ][kk];
            float q1 = Qs[ty + 16][kk];
            float q2 = Qs[ty + 32][kk];
            float b0 = Ks[tx     ][kk];
            float b1 = Ks[tx + 16][kk];
            float b2 = Ks[tx + 32][kk];
            acc[0][0] = fmaf(q0, b0, acc[0][0]);
            acc[0][1] = fmaf(q0, b1, acc[0][1]);
            acc[0][2] = fmaf(q0, b2, acc[0][2]);
            acc[1][0] = fmaf(q1, b0, acc[1][0]);
            acc[1][1] = fmaf(q1, b1, acc[1][1]);
            acc[1][2] = fmaf(q1, b2, acc[1][2]);
            acc[2][0] = fmaf(q2, b0, acc[2][0]);
            acc[2][1] = fmaf(q2, b1, acc[2][1]);
            acc[2][2] = fmaf(q2, b2, acc[2][2]);
        }
        __syncthreads();
    }

    float* sp = &g_Spart[chunk][bh][0];
#pragma unroll
    for (int i = 0; i < 3; i++)
#pragma unroll
        for (int j = 0; j < 3; j++)
            sp[(ty + 16 * i) * DH + tx + 16 * j] = acc[i][j];
}

// ---------------------------------------------------------------------------
// Attention phase 2: reduce partials, apply temperature, row softmax.
// grid = B_*NH, 64 threads (one per row, 48 active).
// ---------------------------------------------------------------------------
__global__ __launch_bounds__(64)
void attn_softmax(const float* __restrict__ temp)
{
    const int bh = blockIdx.x;
    const int h  = bh & 7;
    const int r  = threadIdx.x;
    if (r >= DH) return;
    const float tv = temp[h];

    float vals[DH];
#pragma unroll
    for (int c = 0; c < DH; c++) {
        float s = 0.f;
#pragma unroll
        for (int ch = 0; ch < NCH; ch++)
            s += g_Spart[ch][bh][r * DH + c];
        vals[c] = s * tv;
    }
    float m = -INFINITY;
#pragma unroll
    for (int c = 0; c < DH; c++) m = fmaxf(m, vals[c]);
    float sum = 0.f;
#pragma unroll
    for (int c = 0; c < DH; c++) {
        vals[c] = expf(vals[c] - m);
        sum += vals[c];
    }
    float is = 1.f / sum;
#pragma unroll
    for (int c = 0; c < DH; c++)
        g_S[bh][r * DH + c] = vals[c] * is;
}

// ---------------------------------------------------------------------------
// Attention phase 3: O = S_soft @ V over one spatial chunk, written into the
// q-channel region. grid = (NCH, B_*NH), 256 threads, 3x4 per thread.
// ---------------------------------------------------------------------------
__global__ __launch_bounds__(256)
void attn_apply(float* __restrict__ qkv)
{
    const int bh    = blockIdx.y;
    const int b     = bh >> 3;
    const int h     = bh & 7;
    const int chunk = blockIdx.x;
    const int t  = threadIdx.x;
    const int tx = t & 15;
    const int ty = t >> 4;

    float* qb = qkv + ((size_t)b * C3 + h * DH) * HW;     // output region
    const float* vb = qb + (size_t)2 * C_ * HW;

    __shared__ float Ss[DH][49];
    __shared__ float Vs[DH][65];

    for (int i = t; i < DH * DH; i += 256)
        Ss[i / DH][i % DH] = g_S[bh][i];
    __syncthreads();

    const int nb = chunk * CHUNK;
    for (int n0 = 0; n0 < CHUNK; n0 += 64) {
        for (int i = t; i < DH * 16; i += 256) {
            int r  = i >> 4;
            int c4 = (i & 15) * 4;
            float4 v = *(const float4*)&vb[(size_t)r * HW + nb + n0 + c4];
            Vs[r][c4 + 0] = v.x; Vs[r][c4 + 1] = v.y;
            Vs[r][c4 + 2] = v.z; Vs[r][c4 + 3] = v.w;
        }
        __syncthreads();

        float o[3][4];
#pragma unroll
        for (int i = 0; i < 3; i++)
#pragma unroll
            for (int j = 0; j < 4; j++) o[i][j] = 0.f;

#pragma unroll 12
        for (int e = 0; e < DH; e++) {
            float a0 = Ss[ty     ][e];
            float a1 = Ss[ty + 16][e];
            float a2 = Ss[ty + 32][e];
            float v0 = Vs[e][tx     ];
            float v1 = Vs[e][tx + 16];
            float v2 = Vs[e][tx + 32];
            float v3 = Vs[e][tx + 48];
            o[0][0] = fmaf(a0, v0, o[0][0]); o[0][1] = fmaf(a0, v1, o[0][1]);
            o[0][2] = fmaf(a0, v2, o[0][2]); o[0][3] = fmaf(a0, v3, o[0][3]);
            o[1][0] = fmaf(a1, v0, o[1][0]); o[1][1] = fmaf(a1, v1, o[1][1]);
            o[1][2] = fmaf(a1, v2, o[1][2]); o[1][3] = fmaf(a1, v3, o[1][3]);
            o[2][0] = fmaf(a2, v0, o[2][0]); o[2][1] = fmaf(a2, v1, o[2][1]);
            o[2][2] = fmaf(a2, v2, o[2][2]); o[2][3] = fmaf(a2, v3, o[2][3]);
        }

#pragma unroll
        for (int i = 0; i < 3; i++)
#pragma unroll
            for (int j = 0; j < 4; j++)
                qb[(size_t)(ty + 16 * i) * HW + nb + n0 + tx + 16 * j] = o[i][j];
        __syncthreads();
    }
}

// ---------------------------------------------------------------------------
extern "C" void kernel_launch(void* const* d_in, const int* in_sizes, int n_in,
                              void* d_out, int out_size)
{
    const float* x      = (const float*)d_in[0];   // (16,384,64,64)
    const float* w_qkv  = (const float*)d_in[1];   // (1152,384)
    const float* w_dw   = (const float*)d_in[2];   // (1152,1,3,3)
    const float* w_proj = (const float*)d_in[3];   // (384,384)
    const float* temp   = (const float*)d_in[4];   // (1,8,1,1)
    float* out = (float*)d_out;                    // (16,384,64,64)

    float* qkv;
    float* inv;
    cudaGetSymbolAddress((void**)&qkv, g_qkv);
    cudaGetSymbolAddress((void**)&inv, g_inv);

    // 1) qkv = w_qkv @ x   (per batch: M=1152, K=384, N=4096)
    {
        dim3 grid(HW / 128, C3 / 128, B_);
        sgemm128<<<grid, 256>>>(w_qkv, x, qkv, C3, HW, C_,
                                (size_t)C_ * HW, (size_t)C3 * HW);
    }
    // 2) depthwise 3x3 in place + fused q/k inv L2 norms
    dwconv3x3<<<B_ * C3, 256>>>(qkv, w_dw, inv);
    // 3) attention scores (split-K partials)
    {
        dim3 grid(NCH, B_ * NH);
        attn_scores<<<grid, 256>>>(qkv, inv);
    }
    // 4) reduce + temperature + softmax
    attn_softmax<<<B_ * NH, 64>>>(temp);
    // 5) O = S @ V into q region
    {
        dim3 grid(NCH, B_ * NH);
        attn_apply<<<grid, 256>>>(qkv);
    }
    // 6) out = w_proj @ attn_out  (per batch: M=384, K=384, N=4096)
    {
        dim3 grid(HW / 128, C_ / 128, B_);
        sgemm128<<<grid, 256>>>(w_proj, qkv, out, C_, HW, C_,
                                (size_t)C3 * HW, (size_t)C_ * HW);
    }
}

// round 4
// speedup vs baseline: 2.1321x; 1.7057x over previous
#include <cuda_runtime.h>
#include <cuda.h>
#include <cuda_bf16.h>
#include <math.h>
#include <stdint.h>

// Problem constants (fixed shapes)
#define B_   16
#define C_   384
#define C3   1152
#define HW   4096
#define NH   8
#define DH   48
#define NCH  8
#define CHUNK 512
#define EPSN 1e-12f
#define KTOT 384

// ---------------- scratch (__device__ globals; no runtime alloc) -----------
__device__ __align__(128) float g_qkv[(size_t)B_ * C3 * HW];        // 302 MB
__device__ float g_inv[B_ * 2 * C_];
__device__ float g_Spart[NCH][B_ * NH][DH * DH];
__device__ float g_S[B_ * NH][DH * DH];
__device__ __align__(128) __nv_bfloat16 g_W0[C3 * C_];
__device__ __align__(128) __nv_bfloat16 g_W1[C3 * C_];
__device__ __align__(128) __nv_bfloat16 g_T0[(size_t)B_ * HW * C_]; // 50 MB
__device__ __align__(128) __nv_bfloat16 g_T1[(size_t)B_ * HW * C_];
__device__ __align__(128) __nv_bfloat16 g_We0[B_ * C_ * C_];
__device__ __align__(128) __nv_bfloat16 g_We1[B_ * C_ * C_];

// ---------------- warp-MMA helpers (portable sm_100 ISA) -------------------
__device__ __forceinline__ uint32_t smem_u32(const void* p) {
    uint32_t a;
    asm("{ .reg .u64 t; cvta.to.shared.u64 t, %1; cvt.u32.u64 %0, t; }"
        : "=r"(a) : "l"(p));
    return a;
}
__device__ __forceinline__ void ldm_x4(uint32_t* r, uint32_t addr) {
    asm volatile("ldmatrix.sync.aligned.m8n8.x4.shared.b16 {%0,%1,%2,%3}, [%4];"
        : "=r"(r[0]), "=r"(r[1]), "=r"(r[2]), "=r"(r[3]) : "r"(addr));
}
__device__ __forceinline__ void mma16816(float* c, const uint32_t* a, const uint32_t* b) {
    asm volatile(
        "mma.sync.aligned.m16n8k16.row.col.f32.bf16.bf16.f32 "
        "{%0,%1,%2,%3}, {%4,%5,%6,%7}, {%8,%9}, {%0,%1,%2,%3};"
        : "+f"(c[0]), "+f"(c[1]), "+f"(c[2]), "+f"(c[3])
        : "r"(a[0]), "r"(a[1]), "r"(a[2]), "r"(a[3]), "r"(b[0]), "r"(b[1]));
}

// ---------------------------------------------------------------------------
// bf16-split GEMM via mma.sync: C[b][M,4096] = (Ah+Al)[M,384] @ (Bh+Bl)[4096,384]^T
// 3-term: Ah*Bh + Ah*Bl + Al*Bh.  Block 128x128x32, 8 warps (2Mx4N), warp 64x32.
// A row-major [M][384]; B row-major [N=4096][384] (i.e. col-major operand).
// ---------------------------------------------------------------------------
#define LDT 40   // smem row stride (elements) for 32-wide k tile
__global__ __launch_bounds__(256, 1)
void gemm_mma(const __nv_bfloat16* __restrict__ A0g, const __nv_bfloat16* __restrict__ A1g,
              size_t aBatch,
              const __nv_bfloat16* __restrict__ B0g, const __nv_bfloat16* __restrict__ B1g,
              float* __restrict__ Cg, size_t cBatch)
{
    __shared__ __nv_bfloat16 sA[2][128][LDT];
    __shared__ __nv_bfloat16 sB[2][128][LDT];

    const int t    = threadIdx.x;
    const int lane = t & 31;
    const int wid  = t >> 5;
    const int b    = blockIdx.z;
    const int m0   = blockIdx.y * 128;
    const int n0   = blockIdx.x * 128;
    const int warpM = (wid >> 2) * 64;
    const int warpN = (wid & 3) * 32;

    const __nv_bfloat16* Asrc[2] = { A0g + (size_t)b * aBatch + (size_t)m0 * KTOT,
                                     A1g + (size_t)b * aBatch + (size_t)m0 * KTOT };
    const __nv_bfloat16* Bsrc[2] = { B0g + (size_t)b * HW * KTOT + (size_t)n0 * KTOT,
                                     B1g + (size_t)b * HW * KTOT + (size_t)n0 * KTOT };
    float* Cp = Cg + (size_t)b * cBatch;

    // per-thread load coords: rows r, r+64 ; 8-col chunk c8
    const int lr8 = t >> 2;           // 0..63
    const int c8  = (t & 3) * 8;

    // ldmatrix base offsets (bytes)
    const int g  = lane >> 3;
    const int lr = lane & 7;
    const uint32_t aBase = smem_u32(&sA[0][0][0]);
    const uint32_t bBase = smem_u32(&sB[0][0][0]);
    const uint32_t aOff = ((warpM + (g & 1) * 8 + lr) * LDT + (g >> 1) * 8) * 2;
    const uint32_t bOff = ((warpN + (g >> 1) * 8 + lr) * LDT + (g & 1) * 8) * 2;
    const uint32_t termSz = 128 * LDT * 2;   // bytes per term plane

    float acc[4][4][4];
#pragma unroll
    for (int i = 0; i < 4; i++)
#pragma unroll
        for (int j = 0; j < 4; j++)
#pragma unroll
            for (int e = 0; e < 4; e++) acc[i][j][e] = 0.f;

    uint4 pa[2][2], pb[2][2];
#pragma unroll
    for (int tm = 0; tm < 2; tm++)
#pragma unroll
        for (int i = 0; i < 2; i++) {
            pa[tm][i] = *(const uint4*)&Asrc[tm][(size_t)(lr8 + i * 64) * KTOT + c8];
            pb[tm][i] = *(const uint4*)&Bsrc[tm][(size_t)(lr8 + i * 64) * KTOT + c8];
        }

    for (int kt = 0; kt < KTOT / 32; kt++) {
#pragma unroll
        for (int tm = 0; tm < 2; tm++)
#pragma unroll
            for (int i = 0; i < 2; i++) {
                *(uint4*)&sA[tm][lr8 + i * 64][c8] = pa[tm][i];
                *(uint4*)&sB[tm][lr8 + i * 64][c8] = pb[tm][i];
            }
        __syncthreads();

        if (kt + 1 < KTOT / 32) {
            const int k0 = (kt + 1) * 32;
#pragma unroll
            for (int tm = 0; tm < 2; tm++)
#pragma unroll
                for (int i = 0; i < 2; i++) {
                    pa[tm][i] = *(const uint4*)&Asrc[tm][(size_t)(lr8 + i * 64) * KTOT + k0 + c8];
                    pb[tm][i] = *(const uint4*)&Bsrc[tm][(size_t)(lr8 + i * 64) * KTOT + k0 + c8];
                }
        }

#pragma unroll
        for (int k16 = 0; k16 < 2; k16++) {
            const uint32_t kb = k16 * 16 * 2;
            uint32_t Ah[4][4], Al[4][4], Bh[4][2], Bl[4][2];
#pragma unroll
            for (int i = 0; i < 4; i++) {
                ldm_x4(Ah[i], aBase + aOff + (uint32_t)(i * 16 * LDT * 2) + kb);
                ldm_x4(Al[i], aBase + termSz + aOff + (uint32_t)(i * 16 * LDT * 2) + kb);
            }
#pragma unroll
            for (int p = 0; p < 2; p++) {
                uint32_t r[4];
                ldm_x4(r, bBase + bOff + (uint32_t)(p * 16 * LDT * 2) + kb);
                Bh[p * 2][0] = r[0]; Bh[p * 2][1] = r[1];
                Bh[p * 2 + 1][0] = r[2]; Bh[p * 2 + 1][1] = r[3];
                ldm_x4(r, bBase + termSz + bOff + (uint32_t)(p * 16 * LDT * 2) + kb);
                Bl[p * 2][0] = r[0]; Bl[p * 2][1] = r[1];
                Bl[p * 2 + 1][0] = r[2]; Bl[p * 2 + 1][1] = r[3];
            }
#pragma unroll
            for (int i = 0; i < 4; i++)
#pragma unroll
                for (int j = 0; j < 4; j++) {
                    mma16816(acc[i][j], Ah[i], Bh[j]);
                    mma16816(acc[i][j], Ah[i], Bl[j]);
                    mma16816(acc[i][j], Al[i], Bh[j]);
                }
        }
        __syncthreads();
    }

    // epilogue: float2 stores, thread (row = t/4 within frag, col pair = 2*(t%4))
    const int erow = lane >> 2;
    const int ecol = (lane & 3) * 2;
#pragma unroll
    for (int i = 0; i < 4; i++)
#pragma unroll
        for (int j = 0; j < 4; j++) {
            float* base = Cp + (size_t)(m0 + warpM + i * 16 + erow) * HW
                             + n0 + warpN + j * 8 + ecol;
            *(float2*)base = make_float2(acc[i][j][0], acc[i][j][1]);
            *(float2*)(base + 8 * HW) = make_float2(acc[i][j][2], acc[i][j][3]);
        }
}

// ---------------------------------------------------------------------------
// W fp32 -> bf16 hi/lo split (elementwise)
// ---------------------------------------------------------------------------
__global__ void wconvert(const float* __restrict__ src,
                         __nv_bfloat16* __restrict__ d0,
                         __nv_bfloat16* __restrict__ d1, int n)
{
    int i = blockIdx.x * blockDim.x + threadIdx.x;
    if (i < n) {
        float v = src[i];
        __nv_bfloat16 h = __float2bfloat16(v);
        d0[i] = h;
        d1[i] = __float2bfloat16(v - __bfloat162float(h));
    }
}

// ---------------------------------------------------------------------------
// Transpose + split: src[b][384, 4096] fp32 -> dst[b][4096, 384] bf16 x2.
// ---------------------------------------------------------------------------
__global__ __launch_bounds__(256)
void transconv(const float* __restrict__ src, size_t srcBatch,
               __nv_bfloat16* __restrict__ d0, __nv_bfloat16* __restrict__ d1)
{
    __shared__ float s[64][33];
    const int t  = threadIdx.x;
    const int n0 = blockIdx.x * 32;
    const int c0 = blockIdx.y * 64;
    const int b  = blockIdx.z;
    const float* sp = src + (size_t)b * srcBatch;

#pragma unroll
    for (int it = 0; it < 8; it++) {
        int i = t + it * 256;
        int r = i >> 5, col = i & 31;
        s[r][col] = sp[(size_t)(c0 + r) * HW + n0 + col];
    }
    __syncthreads();

    __nv_bfloat16* o0 = d0 + (size_t)b * HW * KTOT;
    __nv_bfloat16* o1 = d1 + (size_t)b * HW * KTOT;
#pragma unroll
    for (int it = 0; it < 4; it++) {
        int i = t + it * 256;
        int n = i >> 5, cp = i & 31;
        float va = s[2 * cp][n], vb = s[2 * cp + 1][n];
        __nv_bfloat16 ha = __float2bfloat16(va);
        __nv_bfloat16 hb = __float2bfloat16(vb);
        __nv_bfloat16 la = __float2bfloat16(va - __bfloat162float(ha));
        __nv_bfloat16 lb = __float2bfloat16(vb - __bfloat162float(hb));
        size_t idx = (size_t)(n0 + n) * KTOT + c0 + 2 * cp;
        uint32_t ph = (uint32_t)__bfloat16_as_ushort(ha) |
                      ((uint32_t)__bfloat16_as_ushort(hb) << 16);
        uint32_t pl = (uint32_t)__bfloat16_as_ushort(la) |
                      ((uint32_t)__bfloat16_as_ushort(lb) << 16);
        *(uint32_t*)&o0[idx] = ph;
        *(uint32_t*)&o1[idx] = pl;
    }
}

// ---------------------------------------------------------------------------
// Depthwise 3x3 SAME conv in place + fused q/k inv L2 norms
// ---------------------------------------------------------------------------
__global__ __launch_bounds__(256)
void dwconv3x3(float* __restrict__ qkv, const float* __restrict__ wdw,
               float* __restrict__ inv)
{
    const int plane = blockIdx.x;
    const int b     = plane / C3;
    const int ch    = plane % C3;
    float* p = qkv + (size_t)plane * HW;

    __shared__ float s[66][66];
    const int t = threadIdx.x;

    for (int i = t; i < 66 * 66; i += 256) ((float*)s)[i] = 0.f;
    __syncthreads();
    for (int i = t; i < HW; i += 256) {
        int y = i >> 6, x = i & 63;
        s[y + 1][x + 1] = p[i];
    }

    float w[9];
#pragma unroll
    for (int j = 0; j < 9; j++) w[j] = wdw[ch * 9 + j];
    __syncthreads();

    float ss = 0.f;
    for (int i = t; i < HW; i += 256) {
        int y = i >> 6, x = i & 63;
        float acc = 0.f;
#pragma unroll
        for (int dy = 0; dy < 3; dy++)
#pragma unroll
            for (int dx = 0; dx < 3; dx++)
                acc = fmaf(s[y + dy][x + dx], w[dy * 3 + dx], acc);
        p[i] = acc;
        ss = fmaf(acc, acc, ss);
    }

    if (ch < 2 * C_) {
        for (int off = 16; off > 0; off >>= 1)
            ss += __shfl_down_sync(0xffffffffu, ss, off);
        __shared__ float red[8];
        if ((t & 31) == 0) red[t >> 5] = ss;
        __syncthreads();
        if (t == 0) {
            float tot = 0.f;
#pragma unroll
            for (int i = 0; i < 8; i++) tot += red[i];
            inv[b * 2 * C_ + ch] = 1.f / fmaxf(sqrtf(tot), EPSN);
        }
    }
}

// ---------------------------------------------------------------------------
// Attention scores split-K partials
// ---------------------------------------------------------------------------
__global__ __launch_bounds__(256)
void attn_scores(const float* __restrict__ qkv, const float* __restrict__ inv)
{
    const int bh    = blockIdx.y;
    const int b     = bh >> 3;
    const int h     = bh & 7;
    const int chunk = blockIdx.x;
    const int t  = threadIdx.x;
    const int tx = t & 15;
    const int ty = t >> 4;

    const float* qbase = qkv + ((size_t)b * C3 + h * DH) * HW;
    const float* kbase = qbase + (size_t)C_ * HW;

    __shared__ float Qs[DH][65];
    __shared__ float Ks[DH][65];
    __shared__ float ivq[DH], ivk[DH];

    if (t < DH)            ivq[t] = inv[b * 2 * C_ + h * DH + t];
    else if (t < 2 * DH)   ivk[t - DH] = inv[b * 2 * C_ + C_ + h * DH + (t - DH)];
    __syncthreads();

    float acc[3][3];
#pragma unroll
    for (int i = 0; i < 3; i++)
#pragma unroll
        for (int j = 0; j < 3; j++) acc[i][j] = 0.f;

    const int kb = chunk * CHUNK;
    for (int k0 = 0; k0 < CHUNK; k0 += 64) {
        for (int i = t; i < DH * 16; i += 256) {
            int r  = i >> 4;
            int c4 = (i & 15) * 4;
            float4 qv = *(const float4*)&qbase[(size_t)r * HW + kb + k0 + c4];
            float4 kv = *(const float4*)&kbase[(size_t)r * HW + kb + k0 + c4];
            float sq = ivq[r], sk = ivk[r];
            Qs[r][c4 + 0] = qv.x * sq; Qs[r][c4 + 1] = qv.y * sq;
            Qs[r][c4 + 2] = qv.z * sq; Qs[r][c4 + 3] = qv.w * sq;
            Ks[r][c4 + 0] = kv.x * sk; Ks[r][c4 + 1] = kv.y * sk;
            Ks[r][c4 + 2] = kv.z * sk; Ks[r][c4 + 3] = kv.w * sk;
        }
        __syncthreads();

#pragma unroll 16
        for (int kk = 0; kk < 64; kk++) {
            float q0 = Qs[ty     ][kk];
            float q1 = Qs[ty + 16][kk];
            float q2 = Qs[ty + 32][kk];
            float b0 = Ks[tx     ][kk];
            float b1 = Ks[tx + 16][kk];
            float b2 = Ks[tx + 32][kk];
            acc[0][0] = fmaf(q0, b0, acc[0][0]);
            acc[0][1] = fmaf(q0, b1, acc[0][1]);
            acc[0][2] = fmaf(q0, b2, acc[0][2]);
            acc[1][0] = fmaf(q1, b0, acc[1][0]);
            acc[1][1] = fmaf(q1, b1, acc[1][1]);
            acc[1][2] = fmaf(q1, b2, acc[1][2]);
            acc[2][0] = fmaf(q2, b0, acc[2][0]);
            acc[2][1] = fmaf(q2, b1, acc[2][1]);
            acc[2][2] = fmaf(q2, b2, acc[2][2]);
        }
        __syncthreads();
    }

    float* sp = &g_Spart[chunk][bh][0];
#pragma unroll
    for (int i = 0; i < 3; i++)
#pragma unroll
        for (int j = 0; j < 3; j++)
            sp[(ty + 16 * i) * DH + tx + 16 * j] = acc[i][j];
}

__global__ __launch_bounds__(64)
void attn_softmax(const float* __restrict__ temp)
{
    const int bh = blockIdx.x;
    const int h  = bh & 7;
    const int r  = threadIdx.x;
    if (r >= DH) return;
    const float tv = temp[h];

    float vals[DH];
#pragma unroll
    for (int c = 0; c < DH; c++) {
        float s = 0.f;
#pragma unroll
        for (int ch = 0; ch < NCH; ch++)
            s += g_Spart[ch][bh][r * DH + c];
        vals[c] = s * tv;
    }
    float m = -INFINITY;
#pragma unroll
    for (int c = 0; c < DH; c++) m = fmaxf(m, vals[c]);
    float sum = 0.f;
#pragma unroll
    for (int c = 0; c < DH; c++) {
        vals[c] = expf(vals[c] - m);
        sum += vals[c];
    }
    float is = 1.f / sum;
#pragma unroll
    for (int c = 0; c < DH; c++)
        g_S[bh][r * DH + c] = vals[c] * is;
}

// ---------------------------------------------------------------------------
// W_eff[b] = W_proj @ blockdiag(A_soft[b]) ; split to bf16. grid = B_*NH.
// ---------------------------------------------------------------------------
__global__ __launch_bounds__(256)
void weff_kernel(const float* __restrict__ wp,
                 __nv_bfloat16* __restrict__ e0, __nv_bfloat16* __restrict__ e1)
{
    const int bh = blockIdx.x;
    const int b  = bh >> 3;
    const int h  = bh & 7;
    const int t  = threadIdx.x;

    __shared__ float As[DH][DH + 1];
    for (int i = t; i < DH * DH; i += 256)
        As[i / DH][i % DH] = g_S[bh][i];
    __syncthreads();

    for (int o = t; o < C_; o += 256) {
        float wrow[DH];
#pragma unroll
        for (int d = 0; d < DH; d++) wrow[d] = wp[(size_t)o * C_ + h * DH + d];
#pragma unroll 4
        for (int e = 0; e < DH; e++) {
            float acc = 0.f;
#pragma unroll
            for (int d = 0; d < DH; d++) acc = fmaf(wrow[d], As[d][e], acc);
            size_t idx = ((size_t)b * C_ + o) * C_ + h * DH + e;
            __nv_bfloat16 hi = __float2bfloat16(acc);
            e0[idx] = hi;
            e1[idx] = __float2bfloat16(acc - __bfloat162float(hi));
        }
    }
}

// ---------------------------------------------------------------------------
extern "C" void kernel_launch(void* const* d_in, const int* in_sizes, int n_in,
                              void* d_out, int out_size)
{
    const float* x      = (const float*)d_in[0];
    const float* w_qkv  = (const float*)d_in[1];
    const float* w_dw   = (const float*)d_in[2];
    const float* w_proj = (const float*)d_in[3];
    const float* temp   = (const float*)d_in[4];
    float* out = (float*)d_out;

    float *qkv, *inv;
    __nv_bfloat16 *W0, *W1, *T0, *T1, *We0, *We1;
    cudaGetSymbolAddress((void**)&qkv, g_qkv);
    cudaGetSymbolAddress((void**)&inv, g_inv);
    cudaGetSymbolAddress((void**)&W0, g_W0);
    cudaGetSymbolAddress((void**)&W1, g_W1);
    cudaGetSymbolAddress((void**)&T0, g_T0);
    cudaGetSymbolAddress((void**)&T1, g_T1);
    cudaGetSymbolAddress((void**)&We0, g_We0);
    cudaGetSymbolAddress((void**)&We1, g_We1);

    // 1) split W_qkv to bf16 pair
    wconvert<<<(C3 * C_ + 255) / 256, 256>>>(w_qkv, W0, W1, C3 * C_);
    // 2) transpose+split x -> XT
    transconv<<<dim3(HW / 32, C_ / 64, B_), 256>>>(x, (size_t)C_ * HW, T0, T1);
    // 3) qkv = W_qkv @ x via mma.sync
    gemm_mma<<<dim3(HW / 128, C3 / 128, B_), 256>>>(
        W0, W1, 0, T0, T1, qkv, (size_t)C3 * HW);
    // 4) dwconv + fused norms
    dwconv3x3<<<B_ * C3, 256>>>(qkv, w_dw, inv);
    // 5) attention scores + softmax
    attn_scores<<<dim3(NCH, B_ * NH), 256>>>(qkv, inv);
    attn_softmax<<<B_ * NH, 64>>>(temp);
    // 6) W_eff = W_proj . blockdiag(A)
    weff_kernel<<<B_ * NH, 256>>>(w_proj, We0, We1);
    // 7) transpose+split V -> VT (reuse T buffers)
    transconv<<<dim3(HW / 32, C_ / 64, B_), 256>>>(
        qkv + (size_t)2 * C_ * HW, (size_t)C3 * HW, T0, T1);
    // 8) out = W_eff[b] @ V via mma.sync
    gemm_mma<<<dim3(HW / 128, C_ / 128, B_), 256>>>(
        We0, We1, (size_t)C_ * C_, T0, T1, out, (size_t)C_ * HW);
}

// round 5
// speedup vs baseline: 2.3277x; 1.0917x over previous
#include <cuda_runtime.h>
#include <cuda.h>
#include <cuda_bf16.h>
#include <math.h>
#include <stdint.h>

// Problem constants (fixed shapes)
#define B_   16
#define C_   384
#define C3   1152
#define HW   4096
#define NH   8
#define DH   48
#define NCH  8
#define CHUNK 512
#define EPSN 1e-12f
#define KTOT 384

// GEMM smem geometry
#define LDA 40
#define LDB 136
#define A_TERM_SZ (128 * LDA * 2)          // 10240
#define B_TERM_SZ (32 * LDB * 2)           // 8704
#define B_OFF     (2 * A_TERM_SZ)          // 20480
#define SST       (B_OFF + 2 * B_TERM_SZ)  // 37888 per stage
#define GSMEM     (2 * SST)                // 75776

// ---------------- scratch (__device__ globals; no runtime alloc) -----------
__device__ __align__(128) float g_qkv[(size_t)B_ * C3 * HW];        // 302 MB
__device__ float g_inv[B_ * 2 * C_];
__device__ float g_Spart[NCH][B_ * NH][DH * DH];
__device__ float g_S[B_ * NH][DH * DH];
__device__ __align__(128) __nv_bfloat16 g_W0[C3 * C_];
__device__ __align__(128) __nv_bfloat16 g_W1[C3 * C_];
__device__ __align__(128) __nv_bfloat16 g_T0[(size_t)B_ * C_ * HW]; // X split, then V split
__device__ __align__(128) __nv_bfloat16 g_T1[(size_t)B_ * C_ * HW];
__device__ __align__(128) __nv_bfloat16 g_We0[B_ * C_ * C_];
__device__ __align__(128) __nv_bfloat16 g_We1[B_ * C_ * C_];

// ---------------- PTX helpers ----------------------------------------------
__device__ __forceinline__ uint32_t smem_u32(const void* p) {
    uint32_t a;
    asm("{ .reg .u64 t; cvta.to.shared.u64 t, %1; cvt.u32.u64 %0, t; }"
        : "=r"(a) : "l"(p));
    return a;
}
__device__ __forceinline__ void ldm_x4(uint32_t* r, uint32_t addr) {
    asm volatile("ldmatrix.sync.aligned.m8n8.x4.shared.b16 {%0,%1,%2,%3}, [%4];"
        : "=r"(r[0]), "=r"(r[1]), "=r"(r[2]), "=r"(r[3]) : "r"(addr));
}
__device__ __forceinline__ void ldm_x4_t(uint32_t* r, uint32_t addr) {
    asm volatile("ldmatrix.sync.aligned.m8n8.x4.trans.shared.b16 {%0,%1,%2,%3}, [%4];"
        : "=r"(r[0]), "=r"(r[1]), "=r"(r[2]), "=r"(r[3]) : "r"(addr));
}
__device__ __forceinline__ void mma16816(float* c, const uint32_t* a, const uint32_t* b) {
    asm volatile(
        "mma.sync.aligned.m16n8k16.row.col.f32.bf16.bf16.f32 "
        "{%0,%1,%2,%3}, {%4,%5,%6,%7}, {%8,%9}, {%0,%1,%2,%3};"
        : "+f"(c[0]), "+f"(c[1]), "+f"(c[2]), "+f"(c[3])
        : "r"(a[0]), "r"(a[1]), "r"(a[2]), "r"(a[3]), "r"(b[0]), "r"(b[1]));
}
__device__ __forceinline__ void cpa16(uint32_t s, const void* g) {
    asm volatile("cp.async.cg.shared.global [%0], [%1], 16;" :: "r"(s), "l"(g));
}
__device__ __forceinline__ void cpa_commit() {
    asm volatile("cp.async.commit_group;");
}
template <int N> __device__ __forceinline__ void cpa_wait() {
    asm volatile("cp.async.wait_group %0;" :: "n"(N));
}

// ---------------------------------------------------------------------------
// bf16-split GEMM, cp.async 2-stage. C[b][M,4096] = (Ah+Al)[M,384]@(Bh+Bl)[384,4096]
// A row-major [m][k]; B planes [k][n] (n contiguous) consumed via ldmatrix.trans.
// 3 terms: Ah*Bh + Ah*Bl + Al*Bh. Block 128x128x32, 8 warps (2Mx4N), warp 64x32.
// ---------------------------------------------------------------------------
__global__ __launch_bounds__(256, 1)
void gemm_mma(const __nv_bfloat16* __restrict__ A0g, const __nv_bfloat16* __restrict__ A1g,
              size_t aBatch,
              const __nv_bfloat16* __restrict__ B0g, const __nv_bfloat16* __restrict__ B1g,
              float* __restrict__ Cg, size_t cBatch)
{
    extern __shared__ char smem[];
    const uint32_t sbase = smem_u32(smem);

    const int t    = threadIdx.x;
    const int lane = t & 31;
    const int wid  = t >> 5;
    const int b    = blockIdx.z;
    const int m0   = blockIdx.y * 128;
    const int n0   = blockIdx.x * 128;
    const int warpM = (wid >> 2) * 64;
    const int warpN = (wid & 3) * 32;

    const __nv_bfloat16* Asrc[2] = { A0g + (size_t)b * aBatch + (size_t)m0 * KTOT,
                                     A1g + (size_t)b * aBatch + (size_t)m0 * KTOT };
    const __nv_bfloat16* Bsrc[2] = { B0g + (size_t)b * C_ * HW,
                                     B1g + (size_t)b * C_ * HW };
    float* Cp = Cg + (size_t)b * cBatch;

    // cp.async chunk coords (8 chunks of 16B per thread per stage)
    const int aterm = t >> 9;            // always 0 for t<256 when combined w/ it
    (void)aterm;

    // ldmatrix lane constants
    const int g  = lane >> 3;
    const int lr = lane & 7;
    const uint32_t aLane = (uint32_t)(((g & 1) * 8 + lr) * LDA + (g >> 1) * 8) * 2;
    const uint32_t bLane = (uint32_t)(((g & 1) * 8 + lr) * LDB + (g >> 1) * 8) * 2;

    float acc[4][4][4];
#pragma unroll
    for (int i = 0; i < 4; i++)
#pragma unroll
        for (int j = 0; j < 4; j++)
#pragma unroll
            for (int e = 0; e < 4; e++) acc[i][j][e] = 0.f;

    // ---- stage loader ----
    auto load_stage = [&](int kt, int stg) {
        const uint32_t sb = sbase + stg * SST;
#pragma unroll
        for (int it = 0; it < 4; it++) {          // A: 1024 chunks
            int c = t + it * 256;
            int term = c >> 9, r = (c >> 2) & 127, kc = c & 3;
            const __nv_bfloat16* gp = Asrc[term] + (size_t)r * KTOT + kt * 32 + kc * 8;
            cpa16(sb + term * A_TERM_SZ + r * (LDA * 2) + kc * 16, gp);
        }
#pragma unroll
        for (int it = 0; it < 4; it++) {          // B: 1024 chunks
            int c = t + it * 256;
            int term = c >> 9, r = (c >> 4) & 31, nc = c & 15;
            const __nv_bfloat16* gp = Bsrc[term] + (size_t)(kt * 32 + r) * HW + n0 + nc * 8;
            cpa16(sb + B_OFF + term * B_TERM_SZ + r * (LDB * 2) + nc * 16, gp);
        }
        cpa_commit();
    };

    load_stage(0, 0);

    const int KT = KTOT / 32;   // 12
    for (int kt = 0; kt < KT; kt++) {
        if (kt + 1 < KT) load_stage(kt + 1, (kt + 1) & 1);
        if (kt + 1 < KT) cpa_wait<1>(); else cpa_wait<0>();
        __syncthreads();

        const uint32_t sb = sbase + (kt & 1) * SST;
#pragma unroll
        for (int k16 = 0; k16 < 2; k16++) {
            uint32_t Ah[4][4], Al[4][4], Bf[2][4][2];
#pragma unroll
            for (int i = 0; i < 4; i++) {
                uint32_t ao = sb + aLane + (uint32_t)((warpM + i * 16) * LDA + k16 * 16) * 2;
                ldm_x4(Ah[i], ao);
                ldm_x4(Al[i], ao + A_TERM_SZ);
            }
#pragma unroll
            for (int term = 0; term < 2; term++)
#pragma unroll
                for (int p = 0; p < 2; p++) {
                    uint32_t r[4];
                    uint32_t bo = sb + B_OFF + term * B_TERM_SZ + bLane
                                + (uint32_t)(k16 * 16 * LDB + warpN + p * 16) * 2;
                    ldm_x4_t(r, bo);
                    Bf[term][p * 2][0] = r[0]; Bf[term][p * 2][1] = r[1];
                    Bf[term][p * 2 + 1][0] = r[2]; Bf[term][p * 2 + 1][1] = r[3];
                }
#pragma unroll
            for (int i = 0; i < 4; i++)
#pragma unroll
                for (int j = 0; j < 4; j++) {
                    mma16816(acc[i][j], Ah[i], Bf[0][j]);
                    mma16816(acc[i][j], Ah[i], Bf[1][j]);
                    mma16816(acc[i][j], Al[i], Bf[0][j]);
                }
        }
        __syncthreads();
    }

    const int erow = lane >> 2;
    const int ecol = (lane & 3) * 2;
#pragma unroll
    for (int i = 0; i < 4; i++)
#pragma unroll
        for (int j = 0; j < 4; j++) {
            float* base = Cp + (size_t)(m0 + warpM + i * 16 + erow) * HW
                             + n0 + warpN + j * 8 + ecol;
            *(float2*)base = make_float2(acc[i][j][0], acc[i][j][1]);
            *(float2*)(base + 8 * HW) = make_float2(acc[i][j][2], acc[i][j][3]);
        }
}

// ---------------------------------------------------------------------------
// elementwise fp32 -> bf16 hi/lo split (W and x)
// ---------------------------------------------------------------------------
__global__ void wconvert(const float* __restrict__ src,
                         __nv_bfloat16* __restrict__ d0,
                         __nv_bfloat16* __restrict__ d1, int n)
{
    int i = blockIdx.x * blockDim.x + threadIdx.x;
    if (i < n) {
        float v = src[i];
        __nv_bfloat16 h = __float2bfloat16(v);
        d0[i] = h;
        d1[i] = __float2bfloat16(v - __bfloat162float(h));
    }
}

__global__ __launch_bounds__(256)
void xsplit(const float* __restrict__ src,
            __nv_bfloat16* __restrict__ d0, __nv_bfloat16* __restrict__ d1, int n4)
{
    int i = blockIdx.x * 256 + threadIdx.x;
    if (i >= n4) return;
    float4 v = ((const float4*)src)[i];
    __nv_bfloat16 h0 = __float2bfloat16(v.x), h1 = __float2bfloat16(v.y);
    __nv_bfloat16 h2 = __float2bfloat16(v.z), h3 = __float2bfloat16(v.w);
    __nv_bfloat16 l0 = __float2bfloat16(v.x - __bfloat162float(h0));
    __nv_bfloat16 l1 = __float2bfloat16(v.y - __bfloat162float(h1));
    __nv_bfloat16 l2 = __float2bfloat16(v.z - __bfloat162float(h2));
    __nv_bfloat16 l3 = __float2bfloat16(v.w - __bfloat162float(h3));
    uint2 hp = make_uint2(
        (uint32_t)__bfloat16_as_ushort(h0) | ((uint32_t)__bfloat16_as_ushort(h1) << 16),
        (uint32_t)__bfloat16_as_ushort(h2) | ((uint32_t)__bfloat16_as_ushort(h3) << 16));
    uint2 lp = make_uint2(
        (uint32_t)__bfloat16_as_ushort(l0) | ((uint32_t)__bfloat16_as_ushort(l1) << 16),
        (uint32_t)__bfloat16_as_ushort(l2) | ((uint32_t)__bfloat16_as_ushort(l3) << 16));
    ((uint2*)d0)[i] = hp;
    ((uint2*)d1)[i] = lp;
}

// ---------------------------------------------------------------------------
// Depthwise 3x3 SAME conv, float4 stencil. q/k: fp32 in-place + fused norms.
// v: bf16 hi/lo split planes (for GEMM2 B operand), no fp32 write.
// ---------------------------------------------------------------------------
__global__ __launch_bounds__(256)
void dwconv3x3(float* __restrict__ qkv, const float* __restrict__ wdw,
               float* __restrict__ inv,
               __nv_bfloat16* __restrict__ V0, __nv_bfloat16* __restrict__ V1)
{
    const int plane = blockIdx.x;
    const int b     = plane / C3;
    const int ch    = plane % C3;
    float* p = qkv + (size_t)plane * HW;

    __shared__ float s[66][72];
    const int t = threadIdx.x;

    for (int i = t; i < 66 * 72 / 2; i += 256)
        ((float2*)s)[i] = make_float2(0.f, 0.f);
    __syncthreads();
    for (int i = t; i < 1024; i += 256) {
        int y = i >> 4, x4 = (i & 15) * 4;
        float4 v = *(const float4*)&p[y * 64 + x4];
        *(float4*)&s[y + 1][x4 + 4] = v;      // col offset +4 keeps alignment; x=-1 halo at col 3
    }

    float w[9];
#pragma unroll
    for (int j = 0; j < 9; j++) w[j] = wdw[ch * 9 + j];
    __syncthreads();

    const bool isv = (ch >= 2 * C_);
    __nv_bfloat16 *v0 = 0, *v1 = 0;
    if (isv) {
        size_t voff = ((size_t)b * C_ + (ch - 2 * C_)) * HW;
        v0 = V0 + voff; v1 = V1 + voff;
    }

    float ss = 0.f;
    for (int i = t; i < 512; i += 256) {
        int y = i >> 3, x8 = (i & 7) * 8;
        float v[3][16];
#pragma unroll
        for (int dy = 0; dy < 3; dy++) {
            *(float4*)&v[dy][0]  = *(float4*)&s[y + dy][x8];
            *(float4*)&v[dy][4]  = *(float4*)&s[y + dy][x8 + 4];
            *(float4*)&v[dy][8]  = *(float4*)&s[y + dy][x8 + 8];
            *(float4*)&v[dy][12] = *(float4*)&s[y + dy][x8 + 12];
        }
        float o[8];
#pragma unroll
        for (int j = 0; j < 8; j++) {
            float a = 0.f;
#pragma unroll
            for (int dy = 0; dy < 3; dy++)
#pragma unroll
                for (int dx = 0; dx < 3; dx++)
                    a = fmaf(v[dy][3 + j + dx], w[dy * 3 + dx], a);
            o[j] = a;
        }
        if (!isv) {
            *(float4*)&p[y * 64 + x8]     = make_float4(o[0], o[1], o[2], o[3]);
            *(float4*)&p[y * 64 + x8 + 4] = make_float4(o[4], o[5], o[6], o[7]);
#pragma unroll
            for (int j = 0; j < 8; j++) ss = fmaf(o[j], o[j], ss);
        } else {
            uint32_t hp[4], lp[4];
#pragma unroll
            for (int j = 0; j < 4; j++) {
                __nv_bfloat16 ha = __float2bfloat16(o[2 * j]);
                __nv_bfloat16 hb = __float2bfloat16(o[2 * j + 1]);
                __nv_bfloat16 la = __float2bfloat16(o[2 * j] - __bfloat162float(ha));
                __nv_bfloat16 lb = __float2bfloat16(o[2 * j + 1] - __bfloat162float(hb));
                hp[j] = (uint32_t)__bfloat16_as_ushort(ha) |
                        ((uint32_t)__bfloat16_as_ushort(hb) << 16);
                lp[j] = (uint32_t)__bfloat16_as_ushort(la) |
                        ((uint32_t)__bfloat16_as_ushort(lb) << 16);
            }
            *(uint4*)&v0[y * 64 + x8] = make_uint4(hp[0], hp[1], hp[2], hp[3]);
            *(uint4*)&v1[y * 64 + x8] = make_uint4(lp[0], lp[1], lp[2], lp[3]);
        }
    }

    if (ch < 2 * C_) {
        for (int off = 16; off > 0; off >>= 1)
            ss += __shfl_down_sync(0xffffffffu, ss, off);
        __shared__ float red[8];
        if ((t & 31) == 0) red[t >> 5] = ss;
        __syncthreads();
        if (t == 0) {
            float tot = 0.f;
#pragma unroll
            for (int i = 0; i < 8; i++) tot += red[i];
            inv[b * 2 * C_ + ch] = 1.f / fmaxf(sqrtf(tot), EPSN);
        }
    }
}

// ---------------------------------------------------------------------------
// Attention scores split-K partials (unchanged, passing)
// ---------------------------------------------------------------------------
__global__ __launch_bounds__(256)
void attn_scores(const float* __restrict__ qkv, const float* __restrict__ inv)
{
    const int bh    = blockIdx.y;
    const int b     = bh >> 3;
    const int h     = bh & 7;
    const int chunk = blockIdx.x;
    const int t  = threadIdx.x;
    const int tx = t & 15;
    const int ty = t >> 4;

    const float* qbase = qkv + ((size_t)b * C3 + h * DH) * HW;
    const float* kbase = qbase + (size_t)C_ * HW;

    __shared__ float Qs[DH][65];
    __shared__ float Ks[DH][65];
    __shared__ float ivq[DH], ivk[DH];

    if (t < DH)            ivq[t] = inv[b * 2 * C_ + h * DH + t];
    else if (t < 2 * DH)   ivk[t - DH] = inv[b * 2 * C_ + C_ + h * DH + (t - DH)];
    __syncthreads();

    float acc[3][3];
#pragma unroll
    for (int i = 0; i < 3; i++)
#pragma unroll
        for (int j = 0; j < 3; j++) acc[i][j] = 0.f;

    const int kb = chunk * CHUNK;
    for (int k0 = 0; k0 < CHUNK; k0 += 64) {
        for (int i = t; i < DH * 16; i += 256) {
            int r  = i >> 4;
            int c4 = (i & 15) * 4;
            float4 qv = *(const float4*)&qbase[(size_t)r * HW + kb + k0 + c4];
            float4 kv = *(const float4*)&kbase[(size_t)r * HW + kb + k0 + c4];
            float sq = ivq[r], sk = ivk[r];
            Qs[r][c4 + 0] = qv.x * sq; Qs[r][c4 + 1] = qv.y * sq;
            Qs[r][c4 + 2] = qv.z * sq; Qs[r][c4 + 3] = qv.w * sq;
            Ks[r][c4 + 0] = kv.x * sk; Ks[r][c4 + 1] = kv.y * sk;
            Ks[r][c4 + 2] = kv.z * sk; Ks[r][c4 + 3] = kv.w * sk;
        }
        __syncthreads();

#pragma unroll 16
        for (int kk = 0; kk < 64; kk++) {
            float q0 = Qs[ty     ][kk];
            float q1 = Qs[ty + 16][kk];
            float q2 = Qs[ty + 32][kk];
            float b0 = Ks[tx     ][kk];
            float b1 = Ks[tx + 16][kk];
            float b2 = Ks[tx + 32][kk];
            acc[0][0] = fmaf(q0, b0, acc[0][0]);
            acc[0][1] = fmaf(q0, b1, acc[0][1]);
            acc[0][2] = fmaf(q0, b2, acc[0][2]);
            acc[1][0] = fmaf(q1, b0, acc[1][0]);
            acc[1][1] = fmaf(q1, b1, acc[1][1]);
            acc[1][2] = fmaf(q1, b2, acc[1][2]);
            acc[2][0] = fmaf(q2, b0, acc[2][0]);
            acc[2][1] = fmaf(q2, b1, acc[2][1]);
            acc[2][2] = fmaf(q2, b2, acc[2][2]);
        }
        __syncthreads();
    }

    float* sp = &g_Spart[chunk][bh][0];
#pragma unroll
    for (int i = 0; i < 3; i++)
#pragma unroll
        for (int j = 0; j < 3; j++)
            sp[(ty + 16 * i) * DH + tx + 16 * j] = acc[i][j];
}

__global__ __launch_bounds__(64)
void attn_softmax(const float* __restrict__ temp)
{
    const int bh = blockIdx.x;
    const int h  = bh & 7;
    const int r  = threadIdx.x;
    if (r >= DH) return;
    const float tv = temp[h];

    float vals[DH];
#pragma unroll
    for (int c = 0; c < DH; c++) {
        float s = 0.f;
#pragma unroll
        for (int ch = 0; ch < NCH; ch++)
            s += g_Spart[ch][bh][r * DH + c];
        vals[c] = s * tv;
    }
    float m = -INFINITY;
#pragma unroll
    for (int c = 0; c < DH; c++) m = fmaxf(m, vals[c]);
    float sum = 0.f;
#pragma unroll
    for (int c = 0; c < DH; c++) {
        vals[c] = expf(vals[c] - m);
        sum += vals[c];
    }
    float is = 1.f / sum;
#pragma unroll
    for (int c = 0; c < DH; c++)
        g_S[bh][r * DH + c] = vals[c] * is;
}

// ---------------------------------------------------------------------------
// W_eff[b] = W_proj @ blockdiag(A_soft[b]) ; split to bf16. grid = B_*NH.
// ---------------------------------------------------------------------------
__global__ __launch_bounds__(256)
void weff_kernel(const float* __restrict__ wp,
                 __nv_bfloat16* __restrict__ e0, __nv_bfloat16* __restrict__ e1)
{
    const int bh = blockIdx.x;
    const int b  = bh >> 3;
    const int h  = bh & 7;
    const int t  = threadIdx.x;

    __shared__ float As[DH][DH + 1];
    for (int i = t; i < DH * DH; i += 256)
        As[i / DH][i % DH] = g_S[bh][i];
    __syncthreads();

    for (int o = t; o < C_; o += 256) {
        float wrow[DH];
#pragma unroll
        for (int d = 0; d < DH; d++) wrow[d] = wp[(size_t)o * C_ + h * DH + d];
#pragma unroll 4
        for (int e = 0; e < DH; e++) {
            float acc = 0.f;
#pragma unroll
            for (int d = 0; d < DH; d++) acc = fmaf(wrow[d], As[d][e], acc);
            size_t idx = ((size_t)b * C_ + o) * C_ + h * DH + e;
            __nv_bfloat16 hi = __float2bfloat16(acc);
            e0[idx] = hi;
            e1[idx] = __float2bfloat16(acc - __bfloat162float(hi));
        }
    }
}

// ---------------------------------------------------------------------------
extern "C" void kernel_launch(void* const* d_in, const int* in_sizes, int n_in,
                              void* d_out, int out_size)
{
    const float* x      = (const float*)d_in[0];
    const float* w_qkv  = (const float*)d_in[1];
    const float* w_dw   = (const float*)d_in[2];
    const float* w_proj = (const float*)d_in[3];
    const float* temp   = (const float*)d_in[4];
    float* out = (float*)d_out;

    float *qkv, *inv;
    __nv_bfloat16 *W0, *W1, *T0, *T1, *We0, *We1;
    cudaGetSymbolAddress((void**)&qkv, g_qkv);
    cudaGetSymbolAddress((void**)&inv, g_inv);
    cudaGetSymbolAddress((void**)&W0, g_W0);
    cudaGetSymbolAddress((void**)&W1, g_W1);
    cudaGetSymbolAddress((void**)&T0, g_T0);
    cudaGetSymbolAddress((void**)&T1, g_T1);
    cudaGetSymbolAddress((void**)&We0, g_We0);
    cudaGetSymbolAddress((void**)&We1, g_We1);

    cudaFuncSetAttribute(gemm_mma, cudaFuncAttributeMaxDynamicSharedMemorySize, GSMEM);

    // 1) split W_qkv ; split x (no transpose needed: B consumed [k][n] via ldmatrix.trans)
    wconvert<<<(C3 * C_ + 255) / 256, 256>>>(w_qkv, W0, W1, C3 * C_);
    xsplit<<<(B_ * C_ * HW / 4 + 255) / 256, 256>>>(x, T0, T1, B_ * C_ * HW / 4);
    // 2) qkv = W_qkv @ x via mma.sync + cp.async
    gemm_mma<<<dim3(HW / 128, C3 / 128, B_), 256, GSMEM>>>(
        W0, W1, 0, T0, T1, qkv, (size_t)C3 * HW);
    // 3) dwconv: q/k fp32 in-place + norms; v -> bf16 split planes (reuse T0/T1)
    dwconv3x3<<<B_ * C3, 256>>>(qkv, w_dw, inv, T0, T1);
    // 4) attention scores + softmax
    attn_scores<<<dim3(NCH, B_ * NH), 256>>>(qkv, inv);
    attn_softmax<<<B_ * NH, 64>>>(temp);
    // 5) W_eff = W_proj . blockdiag(A)
    weff_kernel<<<B_ * NH, 256>>>(w_proj, We0, We1);
    // 6) out = W_eff[b] @ V via mma.sync + cp.async
    gemm_mma<<<dim3(HW / 128, C_ / 128, B_), 256, GSMEM>>>(
        We0, We1, (size_t)C_ * C_, T0, T1, out, (size_t)C_ * HW);
}

// round 6
// speedup vs baseline: 2.3763x; 1.0209x over previous
#include <cuda_runtime.h>
#include <cuda.h>
#include <cuda_bf16.h>
#include <math.h>
#include <stdint.h>

// Problem constants (fixed shapes)
#define B_   16
#define C_   384
#define C3   1152
#define HW   4096
#define NH   8
#define DH   48
#define NCH  8
#define CHUNK 512
#define EPSN 1e-12f
#define KTOT 384

// GEMM smem geometry (3-stage cp.async)
#define LDA 40
#define LDB 136
#define A_TERM_SZ (128 * LDA * 2)          // 10240
#define B_TERM_SZ (32 * LDB * 2)           // 8704
#define B_OFF     (2 * A_TERM_SZ)          // 20480
#define SST       (B_OFF + 2 * B_TERM_SZ)  // 37888 per stage
#define NSTG      3
#define GSMEM     (NSTG * SST)             // 113664

// ---------------- scratch (__device__ globals; no runtime alloc) -----------
__device__ __align__(128) float g_qkv[(size_t)B_ * C3 * HW];        // 302 MB
__device__ float g_inv[B_ * 2 * C_];
__device__ float g_Spart[NCH][B_ * NH][DH * DH];
__device__ float g_S[B_ * NH][DH * DH];
__device__ __align__(128) __nv_bfloat16 g_W0[C3 * C_];
__device__ __align__(128) __nv_bfloat16 g_W1[C3 * C_];
__device__ __align__(128) __nv_bfloat16 g_T0[(size_t)B_ * C_ * HW]; // X split, then V split
__device__ __align__(128) __nv_bfloat16 g_T1[(size_t)B_ * C_ * HW];
__device__ __align__(128) __nv_bfloat16 g_We0[B_ * C_ * C_];
__device__ __align__(128) __nv_bfloat16 g_We1[B_ * C_ * C_];

// ---------------- PTX helpers ----------------------------------------------
__device__ __forceinline__ uint32_t smem_u32(const void* p) {
    uint32_t a;
    asm("{ .reg .u64 t; cvta.to.shared.u64 t, %1; cvt.u32.u64 %0, t; }"
        : "=r"(a) : "l"(p));
    return a;
}
__device__ __forceinline__ void ldm_x4(uint32_t* r, uint32_t addr) {
    asm volatile("ldmatrix.sync.aligned.m8n8.x4.shared.b16 {%0,%1,%2,%3}, [%4];"
        : "=r"(r[0]), "=r"(r[1]), "=r"(r[2]), "=r"(r[3]) : "r"(addr));
}
__device__ __forceinline__ void ldm_x4_t(uint32_t* r, uint32_t addr) {
    asm volatile("ldmatrix.sync.aligned.m8n8.x4.trans.shared.b16 {%0,%1,%2,%3}, [%4];"
        : "=r"(r[0]), "=r"(r[1]), "=r"(r[2]), "=r"(r[3]) : "r"(addr));
}
__device__ __forceinline__ void mma16816(float* c, const uint32_t* a, const uint32_t* b) {
    asm volatile(
        "mma.sync.aligned.m16n8k16.row.col.f32.bf16.bf16.f32 "
        "{%0,%1,%2,%3}, {%4,%5,%6,%7}, {%8,%9}, {%0,%1,%2,%3};"
        : "+f"(c[0]), "+f"(c[1]), "+f"(c[2]), "+f"(c[3])
        : "r"(a[0]), "r"(a[1]), "r"(a[2]), "r"(a[3]), "r"(b[0]), "r"(b[1]));
}
__device__ __forceinline__ void cpa16(uint32_t s, const void* g) {
    asm volatile("cp.async.cg.shared.global [%0], [%1], 16;" :: "r"(s), "l"(g));
}
__device__ __forceinline__ void cpa_commit() {
    asm volatile("cp.async.commit_group;");
}
template <int N> __device__ __forceinline__ void cpa_wait() {
    asm volatile("cp.async.wait_group %0;" :: "n"(N));
}

// ---------------------------------------------------------------------------
// bf16-split GEMM, cp.async 3-stage. C[b][M,4096] = (Ah+Al)[M,384]@(Bh+Bl)[384,4096]
// grid (x = M/128, y = 4096/128, z = batch): consecutive blocks share the B
// tile (same n0) -> L2 reuse.  Block 128x128x32, 8 warps (2Mx4N), warp 64x32.
// ---------------------------------------------------------------------------
__global__ __launch_bounds__(256, 1)
void gemm_mma(const __nv_bfloat16* __restrict__ A0g, const __nv_bfloat16* __restrict__ A1g,
              size_t aBatch,
              const __nv_bfloat16* __restrict__ B0g, const __nv_bfloat16* __restrict__ B1g,
              float* __restrict__ Cg, size_t cBatch)
{
    extern __shared__ char smem[];
    const uint32_t sbase = smem_u32(smem);

    const int t    = threadIdx.x;
    const int lane = t & 31;
    const int wid  = t >> 5;
    const int b    = blockIdx.z;
    const int m0   = blockIdx.x * 128;     // SWAPPED: x = m-tile
    const int n0   = blockIdx.y * 128;     //          y = n-tile
    const int warpM = (wid >> 2) * 64;
    const int warpN = (wid & 3) * 32;

    const __nv_bfloat16* Asrc[2] = { A0g + (size_t)b * aBatch + (size_t)m0 * KTOT,
                                     A1g + (size_t)b * aBatch + (size_t)m0 * KTOT };
    const __nv_bfloat16* Bsrc[2] = { B0g + (size_t)b * C_ * HW,
                                     B1g + (size_t)b * C_ * HW };
    float* Cp = Cg + (size_t)b * cBatch;

    const int g  = lane >> 3;
    const int lr = lane & 7;
    const uint32_t aLane = (uint32_t)(((g & 1) * 8 + lr) * LDA + (g >> 1) * 8) * 2;
    const uint32_t bLane = (uint32_t)(((g & 1) * 8 + lr) * LDB + (g >> 1) * 8) * 2;

    float acc[4][4][4];
#pragma unroll
    for (int i = 0; i < 4; i++)
#pragma unroll
        for (int j = 0; j < 4; j++)
#pragma unroll
            for (int e = 0; e < 4; e++) acc[i][j][e] = 0.f;

    auto load_stage = [&](int kt, int stg) {
        const uint32_t sb = sbase + stg * SST;
#pragma unroll
        for (int it = 0; it < 4; it++) {          // A: 1024 x 16B
            int c = t + it * 256;
            int term = c >> 9, r = (c >> 2) & 127, kc = c & 3;
            const __nv_bfloat16* gp = Asrc[term] + (size_t)r * KTOT + kt * 32 + kc * 8;
            cpa16(sb + term * A_TERM_SZ + r * (LDA * 2) + kc * 16, gp);
        }
#pragma unroll
        for (int it = 0; it < 4; it++) {          // B: 1024 x 16B
            int c = t + it * 256;
            int term = c >> 9, r = (c >> 4) & 31, nc = c & 15;
            const __nv_bfloat16* gp = Bsrc[term] + (size_t)(kt * 32 + r) * HW + n0 + nc * 8;
            cpa16(sb + B_OFF + term * B_TERM_SZ + r * (LDB * 2) + nc * 16, gp);
        }
        cpa_commit();
    };

    const int KT = KTOT / 32;   // 12
    load_stage(0, 0);
    load_stage(1, 1);

    for (int kt = 0; kt < KT; kt++) {
        if (kt + 2 < KT) load_stage(kt + 2, (kt + 2) % NSTG);
        if (kt + 2 < KT)      cpa_wait<2>();
        else if (kt + 1 < KT) cpa_wait<1>();
        else                  cpa_wait<0>();
        __syncthreads();

        const uint32_t sb = sbase + (kt % NSTG) * SST;
#pragma unroll
        for (int k16 = 0; k16 < 2; k16++) {
            uint32_t Ah[4][4], Al[4][4], Bf[2][4][2];
#pragma unroll
            for (int i = 0; i < 4; i++) {
                uint32_t ao = sb + aLane + (uint32_t)((warpM + i * 16) * LDA + k16 * 16) * 2;
                ldm_x4(Ah[i], ao);
                ldm_x4(Al[i], ao + A_TERM_SZ);
            }
#pragma unroll
            for (int term = 0; term < 2; term++)
#pragma unroll
                for (int p = 0; p < 2; p++) {
                    uint32_t r[4];
                    uint32_t bo = sb + B_OFF + term * B_TERM_SZ + bLane
                                + (uint32_t)(k16 * 16 * LDB + warpN + p * 16) * 2;
                    ldm_x4_t(r, bo);
                    Bf[term][p * 2][0] = r[0]; Bf[term][p * 2][1] = r[1];
                    Bf[term][p * 2 + 1][0] = r[2]; Bf[term][p * 2 + 1][1] = r[3];
                }
#pragma unroll
            for (int i = 0; i < 4; i++)
#pragma unroll
                for (int j = 0; j < 4; j++) {
                    mma16816(acc[i][j], Ah[i], Bf[0][j]);
                    mma16816(acc[i][j], Ah[i], Bf[1][j]);
                    mma16816(acc[i][j], Al[i], Bf[0][j]);
                }
        }
        __syncthreads();
    }

    const int erow = lane >> 2;
    const int ecol = (lane & 3) * 2;
#pragma unroll
    for (int i = 0; i < 4; i++)
#pragma unroll
        for (int j = 0; j < 4; j++) {
            float* base = Cp + (size_t)(m0 + warpM + i * 16 + erow) * HW
                             + n0 + warpN + j * 8 + ecol;
            *(float2*)base = make_float2(acc[i][j][0], acc[i][j][1]);
            *(float2*)(base + 8 * HW) = make_float2(acc[i][j][2], acc[i][j][3]);
        }
}

// ---------------------------------------------------------------------------
// elementwise fp32 -> bf16 hi/lo split
// ---------------------------------------------------------------------------
__global__ void wconvert(const float* __restrict__ src,
                         __nv_bfloat16* __restrict__ d0,
                         __nv_bfloat16* __restrict__ d1, int n)
{
    int i = blockIdx.x * blockDim.x + threadIdx.x;
    if (i < n) {
        float v = src[i];
        __nv_bfloat16 h = __float2bfloat16(v);
        d0[i] = h;
        d1[i] = __float2bfloat16(v - __bfloat162float(h));
    }
}

__global__ __launch_bounds__(256)
void xsplit(const float* __restrict__ src,
            __nv_bfloat16* __restrict__ d0, __nv_bfloat16* __restrict__ d1, int n4)
{
    int i = blockIdx.x * 256 + threadIdx.x;
    if (i >= n4) return;
    float4 v = ((const float4*)src)[i];
    __nv_bfloat16 h0 = __float2bfloat16(v.x), h1 = __float2bfloat16(v.y);
    __nv_bfloat16 h2 = __float2bfloat16(v.z), h3 = __float2bfloat16(v.w);
    __nv_bfloat16 l0 = __float2bfloat16(v.x - __bfloat162float(h0));
    __nv_bfloat16 l1 = __float2bfloat16(v.y - __bfloat162float(h1));
    __nv_bfloat16 l2 = __float2bfloat16(v.z - __bfloat162float(h2));
    __nv_bfloat16 l3 = __float2bfloat16(v.w - __bfloat162float(h3));
    uint2 hp = make_uint2(
        (uint32_t)__bfloat16_as_ushort(h0) | ((uint32_t)__bfloat16_as_ushort(h1) << 16),
        (uint32_t)__bfloat16_as_ushort(h2) | ((uint32_t)__bfloat16_as_ushort(h3) << 16));
    uint2 lp = make_uint2(
        (uint32_t)__bfloat16_as_ushort(l0) | ((uint32_t)__bfloat16_as_ushort(l1) << 16),
        (uint32_t)__bfloat16_as_ushort(l2) | ((uint32_t)__bfloat16_as_ushort(l3) << 16));
    ((uint2*)d0)[i] = hp;
    ((uint2*)d1)[i] = lp;
}

// ---------------------------------------------------------------------------
// Depthwise 3x3 SAME conv, row-pair stencil (each thread: 2 rows x 8 cols).
// q/k: fp32 in-place + fused norms.  v: bf16 hi/lo split planes.
// ---------------------------------------------------------------------------
__global__ __launch_bounds__(256)
void dwconv3x3(float* __restrict__ qkv, const float* __restrict__ wdw,
               float* __restrict__ inv,
               __nv_bfloat16* __restrict__ V0, __nv_bfloat16* __restrict__ V1)
{
    const int plane = blockIdx.x;
    const int b     = plane / C3;
    const int ch    = plane % C3;
    float* p = qkv + (size_t)plane * HW;

    __shared__ float s[66][72];
    const int t = threadIdx.x;

    // zero only the halo cells that the stencil actually reads
    if (t < 72)       { s[0][t] = 0.f; s[65][t] = 0.f; }
    else if (t < 136) { s[t - 72 + 1][3]  = 0.f; }
    else if (t < 200) { s[t - 136 + 1][68] = 0.f; }
    // interior fill (disjoint from halo cells above; no sync needed between)
#pragma unroll
    for (int it = 0; it < 4; it++) {
        int i = t + it * 256;
        int y = i >> 4, x4 = (i & 15) * 4;
        float4 v = *(const float4*)&p[y * 64 + x4];
        *(float4*)&s[y + 1][x4 + 4] = v;
    }

    float w[9];
#pragma unroll
    for (int j = 0; j < 9; j++) w[j] = wdw[ch * 9 + j];
    __syncthreads();

    const bool isv = (ch >= 2 * C_);
    __nv_bfloat16 *v0 = 0, *v1 = 0;
    if (isv) {
        size_t voff = ((size_t)b * C_ + (ch - 2 * C_)) * HW;
        v0 = V0 + voff; v1 = V1 + voff;
    }

    // one 2x8 output tile per thread: rows y,y+1 ; cols x8..x8+7
    const int y  = (t >> 3) * 2;
    const int x8 = (t & 7) * 8;

    float v[4][16];
#pragma unroll
    for (int r = 0; r < 4; r++) {
        *(float4*)&v[r][0]  = *(float4*)&s[y + r][x8];
        *(float4*)&v[r][4]  = *(float4*)&s[y + r][x8 + 4];
        *(float4*)&v[r][8]  = *(float4*)&s[y + r][x8 + 8];
        *(float4*)&v[r][12] = *(float4*)&s[y + r][x8 + 12];
    }

    float o[2][8];
#pragma unroll
    for (int rr = 0; rr < 2; rr++)
#pragma unroll
        for (int j = 0; j < 8; j++) {
            float a = 0.f;
#pragma unroll
            for (int dy = 0; dy < 3; dy++)
#pragma unroll
                for (int dx = 0; dx < 3; dx++)
                    a = fmaf(v[rr + dy][3 + j + dx], w[dy * 3 + dx], a);
            o[rr][j] = a;
        }

    float ss = 0.f;
    if (!isv) {
#pragma unroll
        for (int rr = 0; rr < 2; rr++) {
            *(float4*)&p[(y + rr) * 64 + x8]     = make_float4(o[rr][0], o[rr][1], o[rr][2], o[rr][3]);
            *(float4*)&p[(y + rr) * 64 + x8 + 4] = make_float4(o[rr][4], o[rr][5], o[rr][6], o[rr][7]);
#pragma unroll
            for (int j = 0; j < 8; j++) ss = fmaf(o[rr][j], o[rr][j], ss);
        }
    } else {
#pragma unroll
        for (int rr = 0; rr < 2; rr++) {
            uint32_t hp[4], lp[4];
#pragma unroll
            for (int j = 0; j < 4; j++) {
                __nv_bfloat16 ha = __float2bfloat16(o[rr][2 * j]);
                __nv_bfloat16 hb = __float2bfloat16(o[rr][2 * j + 1]);
                __nv_bfloat16 la = __float2bfloat16(o[rr][2 * j] - __bfloat162float(ha));
                __nv_bfloat16 lb = __float2bfloat16(o[rr][2 * j + 1] - __bfloat162float(hb));
                hp[j] = (uint32_t)__bfloat16_as_ushort(ha) |
                        ((uint32_t)__bfloat16_as_ushort(hb) << 16);
                lp[j] = (uint32_t)__bfloat16_as_ushort(la) |
                        ((uint32_t)__bfloat16_as_ushort(lb) << 16);
            }
            *(uint4*)&v0[(y + rr) * 64 + x8] = make_uint4(hp[0], hp[1], hp[2], hp[3]);
            *(uint4*)&v1[(y + rr) * 64 + x8] = make_uint4(lp[0], lp[1], lp[2], lp[3]);
        }
    }

    if (ch < 2 * C_) {
        for (int off = 16; off > 0; off >>= 1)
            ss += __shfl_down_sync(0xffffffffu, ss, off);
        __shared__ float red[8];
        if ((t & 31) == 0) red[t >> 5] = ss;
        __syncthreads();
        if (t == 0) {
            float tot = 0.f;
#pragma unroll
            for (int i = 0; i < 8; i++) tot += red[i];
            inv[b * 2 * C_ + ch] = 1.f / fmaxf(sqrtf(tot), EPSN);
        }
    }
}

// ---------------------------------------------------------------------------
// Attention scores split-K partials (unchanged, passing)
// ---------------------------------------------------------------------------
__global__ __launch_bounds__(256)
void attn_scores(const float* __restrict__ qkv, const float* __restrict__ inv)
{
    const int bh    = blockIdx.y;
    const int b     = bh >> 3;
    const int h     = bh & 7;
    const int chunk = blockIdx.x;
    const int t  = threadIdx.x;
    const int tx = t & 15;
    const int ty = t >> 4;

    const float* qbase = qkv + ((size_t)b * C3 + h * DH) * HW;
    const float* kbase = qbase + (size_t)C_ * HW;

    __shared__ float Qs[DH][65];
    __shared__ float Ks[DH][65];
    __shared__ float ivq[DH], ivk[DH];

    if (t < DH)            ivq[t] = inv[b * 2 * C_ + h * DH + t];
    else if (t < 2 * DH)   ivk[t - DH] = inv[b * 2 * C_ + C_ + h * DH + (t - DH)];
    __syncthreads();

    float acc[3][3];
#pragma unroll
    for (int i = 0; i < 3; i++)
#pragma unroll
        for (int j = 0; j < 3; j++) acc[i][j] = 0.f;

    const int kb = chunk * CHUNK;
    for (int k0 = 0; k0 < CHUNK; k0 += 64) {
        for (int i = t; i < DH * 16; i += 256) {
            int r  = i >> 4;
            int c4 = (i & 15) * 4;
            float4 qv = *(const float4*)&qbase[(size_t)r * HW + kb + k0 + c4];
            float4 kv = *(const float4*)&kbase[(size_t)r * HW + kb + k0 + c4];
            float sq = ivq[r], sk = ivk[r];
            Qs[r][c4 + 0] = qv.x * sq; Qs[r][c4 + 1] = qv.y * sq;
            Qs[r][c4 + 2] = qv.z * sq; Qs[r][c4 + 3] = qv.w * sq;
            Ks[r][c4 + 0] = kv.x * sk; Ks[r][c4 + 1] = kv.y * sk;
            Ks[r][c4 + 2] = kv.z * sk; Ks[r][c4 + 3] = kv.w * sk;
        }
        __syncthreads();

#pragma unroll 16
        for (int kk = 0; kk < 64; kk++) {
            float q0 = Qs[ty     ][kk];
            float q1 = Qs[ty + 16][kk];
            float q2 = Qs[ty + 32][kk];
            float b0 = Ks[tx     ][kk];
            float b1 = Ks[tx + 16][kk];
            float b2 = Ks[tx + 32][kk];
            acc[0][0] = fmaf(q0, b0, acc[0][0]);
            acc[0][1] = fmaf(q0, b1, acc[0][1]);
            acc[0][2] = fmaf(q0, b2, acc[0][2]);
            acc[1][0] = fmaf(q1, b0, acc[1][0]);
            acc[1][1] = fmaf(q1, b1, acc[1][1]);
            acc[1][2] = fmaf(q1, b2, acc[1][2]);
            acc[2][0] = fmaf(q2, b0, acc[2][0]);
            acc[2][1] = fmaf(q2, b1, acc[2][1]);
            acc[2][2] = fmaf(q2, b2, acc[2][2]);
        }
        __syncthreads();
    }

    float* sp = &g_Spart[chunk][bh][0];
#pragma unroll
    for (int i = 0; i < 3; i++)
#pragma unroll
        for (int j = 0; j < 3; j++)
            sp[(ty + 16 * i) * DH + tx + 16 * j] = acc[i][j];
}

__global__ __launch_bounds__(64)
void attn_softmax(const float* __restrict__ temp)
{
    const int bh = blockIdx.x;
    const int h  = bh & 7;
    const int r  = threadIdx.x;
    if (r >= DH) return;
    const float tv = temp[h];

    float vals[DH];
#pragma unroll
    for (int c = 0; c < DH; c++) {
        float s = 0.f;
#pragma unroll
        for (int ch = 0; ch < NCH; ch++)
            s += g_Spart[ch][bh][r * DH + c];
        vals[c] = s * tv;
    }
    float m = -INFINITY;
#pragma unroll
    for (int c = 0; c < DH; c++) m = fmaxf(m, vals[c]);
    float sum = 0.f;
#pragma unroll
    for (int c = 0; c < DH; c++) {
        vals[c] = expf(vals[c] - m);
        sum += vals[c];
    }
    float is = 1.f / sum;
#pragma unroll
    for (int c = 0; c < DH; c++)
        g_S[bh][r * DH + c] = vals[c] * is;
}

// ---------------------------------------------------------------------------
// W_eff[b] = W_proj @ blockdiag(A_soft[b]) ; split to bf16. grid = B_*NH.
// ---------------------------------------------------------------------------
__global__ __launch_bounds__(256)
void weff_kernel(const float* __restrict__ wp,
                 __nv_bfloat16* __restrict__ e0, __nv_bfloat16* __restrict__ e1)
{
    const int bh = blockIdx.x;
    const int b  = bh >> 3;
    const int h  = bh & 7;
    const int t  = threadIdx.x;

    __shared__ float As[DH][DH + 1];
    for (int i = t; i < DH * DH; i += 256)
        As[i / DH][i % DH] = g_S[bh][i];
    __syncthreads();

    for (int o = t; o < C_; o += 256) {
        float wrow[DH];
#pragma unroll
        for (int d = 0; d < DH; d++) wrow[d] = wp[(size_t)o * C_ + h * DH + d];
#pragma unroll 4
        for (int e = 0; e < DH; e++) {
            float acc = 0.f;
#pragma unroll
            for (int d = 0; d < DH; d++) acc = fmaf(wrow[d], As[d][e], acc);
            size_t idx = ((size_t)b * C_ + o) * C_ + h * DH + e;
            __nv_bfloat16 hi = __float2bfloat16(acc);
            e0[idx] = hi;
            e1[idx] = __float2bfloat16(acc - __bfloat162float(hi));
        }
    }
}

// ---------------------------------------------------------------------------
extern "C" void kernel_launch(void* const* d_in, const int* in_sizes, int n_in,
                              void* d_out, int out_size)
{
    const float* x      = (const float*)d_in[0];
    const float* w_qkv  = (const float*)d_in[1];
    const float* w_dw   = (const float*)d_in[2];
    const float* w_proj = (const float*)d_in[3];
    const float* temp   = (const float*)d_in[4];
    float* out = (float*)d_out;

    float *qkv, *inv;
    __nv_bfloat16 *W0, *W1, *T0, *T1, *We0, *We1;
    cudaGetSymbolAddress((void**)&qkv, g_qkv);
    cudaGetSymbolAddress((void**)&inv, g_inv);
    cudaGetSymbolAddress((void**)&W0, g_W0);
    cudaGetSymbolAddress((void**)&W1, g_W1);
    cudaGetSymbolAddress((void**)&T0, g_T0);
    cudaGetSymbolAddress((void**)&T1, g_T1);
    cudaGetSymbolAddress((void**)&We0, g_We0);
    cudaGetSymbolAddress((void**)&We1, g_We1);

    cudaFuncSetAttribute(gemm_mma, cudaFuncAttributeMaxDynamicSharedMemorySize, GSMEM);

    // 1) split W_qkv ; split x
    wconvert<<<(C3 * C_ + 255) / 256, 256>>>(w_qkv, W0, W1, C3 * C_);
    xsplit<<<(B_ * C_ * HW / 4 + 255) / 256, 256>>>(x, T0, T1, B_ * C_ * HW / 4);
    // 2) qkv = W_qkv @ x  (grid: x=m-tiles, y=n-tiles for B-tile L2 reuse)
    gemm_mma<<<dim3(C3 / 128, HW / 128, B_), 256, GSMEM>>>(
        W0, W1, 0, T0, T1, qkv, (size_t)C3 * HW);
    // 3) dwconv: q/k fp32 in-place + norms; v -> bf16 split planes
    dwconv3x3<<<B_ * C3, 256>>>(qkv, w_dw, inv, T0, T1);
    // 4) attention scores + softmax
    attn_scores<<<dim3(NCH, B_ * NH), 256>>>(qkv, inv);
    attn_softmax<<<B_ * NH, 64>>>(temp);
    // 5) W_eff = W_proj . blockdiag(A)
    weff_kernel<<<B_ * NH, 256>>>(w_proj, We0, We1);
    // 6) out = W_eff[b] @ V
    gemm_mma<<<dim3(C_ / 128, HW / 128, B_), 256, GSMEM>>>(
        We0, We1, (size_t)C_ * C_, T0, T1, out, (size_t)C_ * HW);
}

// round 8
// speedup vs baseline: 2.6733x; 1.1250x over previous
#include <cuda_runtime.h>
#include <cuda.h>
#include <cuda_bf16.h>
#include <math.h>
#include <stdint.h>

// Problem constants (fixed shapes)
#define B_   16
#define C_   384
#define C3   1152
#define HW   4096
#define NH   8
#define DH   48
#define NCH  8
#define CHUNK 512
#define EPSN 1e-12f
#define KTOT 384

// GEMM smem geometry: block 128(M) x 256(N) x 32(K), 3-stage cp.async
#define LDA 40
#define LDB 264
#define A_TERM_SZ (128 * LDA * 2)            // 10240
#define B_TERM_SZ (32 * LDB * 2)             // 16896
#define B_OFF     (2 * A_TERM_SZ)            // 20480
#define SST       (B_OFF + 2 * B_TERM_SZ)    // 54272
#define NSTG      3
#define GSMEM     (NSTG * SST)               // 162816

// ---------------- scratch (__device__ globals; no runtime alloc) -----------
__device__ __align__(128) float g_qkv[(size_t)B_ * C3 * HW];        // 302 MB
__device__ float g_inv[B_ * 2 * C_];
__device__ float g_Spart[NCH][B_ * NH][DH * DH];
__device__ float g_S[B_ * NH][DH * DH];
__device__ __align__(128) __nv_bfloat16 g_W0[C3 * C_];
__device__ __align__(128) __nv_bfloat16 g_W1[C3 * C_];
__device__ __align__(128) __nv_bfloat16 g_T0[(size_t)B_ * C_ * HW]; // X split, then V split
__device__ __align__(128) __nv_bfloat16 g_T1[(size_t)B_ * C_ * HW];
__device__ __align__(128) __nv_bfloat16 g_We0[B_ * C_ * C_];
__device__ __align__(128) __nv_bfloat16 g_We1[B_ * C_ * C_];

// ---------------- PTX helpers ----------------------------------------------
__device__ __forceinline__ uint32_t smem_u32(const void* p) {
    uint32_t a;
    asm("{ .reg .u64 t; cvta.to.shared.u64 t, %1; cvt.u32.u64 %0, t; }"
        : "=r"(a) : "l"(p));
    return a;
}
__device__ __forceinline__ void ldm_x4(uint32_t* r, uint32_t addr) {
    asm volatile("ldmatrix.sync.aligned.m8n8.x4.shared.b16 {%0,%1,%2,%3}, [%4];"
        : "=r"(r[0]), "=r"(r[1]), "=r"(r[2]), "=r"(r[3]) : "r"(addr));
}
__device__ __forceinline__ void ldm_x4_t(uint32_t* r, uint32_t addr) {
    asm volatile("ldmatrix.sync.aligned.m8n8.x4.trans.shared.b16 {%0,%1,%2,%3}, [%4];"
        : "=r"(r[0]), "=r"(r[1]), "=r"(r[2]), "=r"(r[3]) : "r"(addr));
}
__device__ __forceinline__ void mma16816(float* c, const uint32_t* a, const uint32_t* b) {
    asm volatile(
        "mma.sync.aligned.m16n8k16.row.col.f32.bf16.bf16.f32 "
        "{%0,%1,%2,%3}, {%4,%5,%6,%7}, {%8,%9}, {%0,%1,%2,%3};"
        : "+f"(c[0]), "+f"(c[1]), "+f"(c[2]), "+f"(c[3])
        : "r"(a[0]), "r"(a[1]), "r"(a[2]), "r"(a[3]), "r"(b[0]), "r"(b[1]));
}
__device__ __forceinline__ void cpa16(uint32_t s, const void* g) {
    asm volatile("cp.async.cg.shared.global [%0], [%1], 16;" :: "r"(s), "l"(g));
}
__device__ __forceinline__ void cpa_commit() {
    asm volatile("cp.async.commit_group;");
}
template <int N> __device__ __forceinline__ void cpa_wait() {
    asm volatile("cp.async.wait_group %0;" :: "n"(N));
}

// ---------------------------------------------------------------------------
// bf16-split GEMM, block 128x256x32, warp 64x64, 3-stage cp.async.
// C[b][M,4096] = (Ah+Al)[M,384] @ (Bh+Bl)[384,4096]; 3 terms.
// grid (x = M/128, y = 4096/256, z = batch) -> consecutive blocks share B tile.
// ---------------------------------------------------------------------------
__global__ __launch_bounds__(256, 1)
void gemm_mma(const __nv_bfloat16* __restrict__ A0g, const __nv_bfloat16* __restrict__ A1g,
              size_t aBatch,
              const __nv_bfloat16* __restrict__ B0g, const __nv_bfloat16* __restrict__ B1g,
              float* __restrict__ Cg, size_t cBatch)
{
    extern __shared__ char smem[];
    const uint32_t sbase = smem_u32(smem);

    const int t    = threadIdx.x;
    const int lane = t & 31;
    const int wid  = t >> 5;
    const int b    = blockIdx.z;
    const int m0   = blockIdx.x * 128;
    const int n0   = blockIdx.y * 256;
    const int warpM = (wid >> 2) * 64;
    const int warpN = (wid & 3) * 64;

    const __nv_bfloat16* Asrc[2] = { A0g + (size_t)b * aBatch + (size_t)m0 * KTOT,
                                     A1g + (size_t)b * aBatch + (size_t)m0 * KTOT };
    const __nv_bfloat16* Bsrc[2] = { B0g + (size_t)b * C_ * HW,
                                     B1g + (size_t)b * C_ * HW };
    float* Cp = Cg + (size_t)b * cBatch;

    const int g  = lane >> 3;
    const int lr = lane & 7;
    const uint32_t aLane = (uint32_t)(((g & 1) * 8 + lr) * LDA + (g >> 1) * 8) * 2;
    const uint32_t bLane = (uint32_t)(((g & 1) * 8 + lr) * LDB + (g >> 1) * 8) * 2;

    float acc[4][8][4];
#pragma unroll
    for (int i = 0; i < 4; i++)
#pragma unroll
        for (int j = 0; j < 8; j++)
#pragma unroll
            for (int e = 0; e < 4; e++) acc[i][j][e] = 0.f;

    auto load_stage = [&](int kt, int stg) {
        const uint32_t sb = sbase + stg * SST;
#pragma unroll
        for (int it = 0; it < 4; it++) {          // A: 1024 x 16B
            int c = t + it * 256;
            int term = c >> 9, r = (c >> 2) & 127, kc = c & 3;
            const __nv_bfloat16* gp = Asrc[term] + (size_t)r * KTOT + kt * 32 + kc * 8;
            cpa16(sb + term * A_TERM_SZ + r * (LDA * 2) + kc * 16, gp);
        }
#pragma unroll
        for (int it = 0; it < 8; it++) {          // B: 2048 x 16B
            int c = t + it * 256;
            int term = c >> 10, j = c & 1023;
            int r = j >> 5, nc = j & 31;
            const __nv_bfloat16* gp = Bsrc[term] + (size_t)(kt * 32 + r) * HW + n0 + nc * 8;
            cpa16(sb + B_OFF + term * B_TERM_SZ + r * (LDB * 2) + nc * 16, gp);
        }
        cpa_commit();
    };

    const int KT = KTOT / 32;   // 12
    load_stage(0, 0);
    load_stage(1, 1);

    for (int kt = 0; kt < KT; kt++) {
        if (kt + 2 < KT) load_stage(kt + 2, (kt + 2) % NSTG);
        if (kt + 2 < KT)      cpa_wait<2>();
        else if (kt + 1 < KT) cpa_wait<1>();
        else                  cpa_wait<0>();
        __syncthreads();

        const uint32_t sb = sbase + (kt % NSTG) * SST;
#pragma unroll
        for (int k16 = 0; k16 < 2; k16++) {
            uint32_t Ah[4][4], Al[4][4];
#pragma unroll
            for (int i = 0; i < 4; i++) {
                uint32_t ao = sb + aLane + (uint32_t)((warpM + i * 16) * LDA + k16 * 16) * 2;
                ldm_x4(Ah[i], ao);
                ldm_x4(Al[i], ao + A_TERM_SZ);
            }
            // ---- B term 0: Ah*B0 + Al*B0 ----
            {
                uint32_t Bf[8][2];
#pragma unroll
                for (int p = 0; p < 4; p++) {
                    uint32_t r[4];
                    uint32_t bo = sb + B_OFF + bLane
                                + (uint32_t)(k16 * 16 * LDB + warpN + p * 16) * 2;
                    ldm_x4_t(r, bo);
                    Bf[p * 2][0] = r[0]; Bf[p * 2][1] = r[1];
                    Bf[p * 2 + 1][0] = r[2]; Bf[p * 2 + 1][1] = r[3];
                }
#pragma unroll
                for (int i = 0; i < 4; i++)
#pragma unroll
                    for (int j = 0; j < 8; j++) {
                        mma16816(acc[i][j], Ah[i], Bf[j]);
                        mma16816(acc[i][j], Al[i], Bf[j]);
                    }
            }
            // ---- B term 1: Ah*B1 ----
            {
                uint32_t Bf[8][2];
#pragma unroll
                for (int p = 0; p < 4; p++) {
                    uint32_t r[4];
                    uint32_t bo = sb + B_OFF + B_TERM_SZ + bLane
                                + (uint32_t)(k16 * 16 * LDB + warpN + p * 16) * 2;
                    ldm_x4_t(r, bo);
                    Bf[p * 2][0] = r[0]; Bf[p * 2][1] = r[1];
                    Bf[p * 2 + 1][0] = r[2]; Bf[p * 2 + 1][1] = r[3];
                }
#pragma unroll
                for (int i = 0; i < 4; i++)
#pragma unroll
                    for (int j = 0; j < 8; j++)
                        mma16816(acc[i][j], Ah[i], Bf[j]);
            }
        }
        __syncthreads();
    }

    const int erow = lane >> 2;
    const int ecol = (lane & 3) * 2;
#pragma unroll
    for (int i = 0; i < 4; i++)
#pragma unroll
        for (int j = 0; j < 8; j++) {
            float* base = Cp + (size_t)(m0 + warpM + i * 16 + erow) * HW
                             + n0 + warpN + j * 8 + ecol;
            *(float2*)base = make_float2(acc[i][j][0], acc[i][j][1]);
            *(float2*)(base + 8 * HW) = make_float2(acc[i][j][2], acc[i][j][3]);
        }
}

// ---------------------------------------------------------------------------
// elementwise fp32 -> bf16 hi/lo split
// ---------------------------------------------------------------------------
__global__ void wconvert(const float* __restrict__ src,
                         __nv_bfloat16* __restrict__ d0,
                         __nv_bfloat16* __restrict__ d1, int n)
{
    int i = blockIdx.x * blockDim.x + threadIdx.x;
    if (i < n) {
        float v = src[i];
        __nv_bfloat16 h = __float2bfloat16(v);
        d0[i] = h;
        d1[i] = __float2bfloat16(v - __bfloat162float(h));
    }
}

__global__ __launch_bounds__(256)
void xsplit(const float* __restrict__ src,
            __nv_bfloat16* __restrict__ d0, __nv_bfloat16* __restrict__ d1, int n4)
{
    int i = blockIdx.x * 256 + threadIdx.x;
    if (i >= n4) return;
    float4 v = ((const float4*)src)[i];
    __nv_bfloat16 h0 = __float2bfloat16(v.x), h1 = __float2bfloat16(v.y);
    __nv_bfloat16 h2 = __float2bfloat16(v.z), h3 = __float2bfloat16(v.w);
    __nv_bfloat16 l0 = __float2bfloat16(v.x - __bfloat162float(h0));
    __nv_bfloat16 l1 = __float2bfloat16(v.y - __bfloat162float(h1));
    __nv_bfloat16 l2 = __float2bfloat16(v.z - __bfloat162float(h2));
    __nv_bfloat16 l3 = __float2bfloat16(v.w - __bfloat162float(h3));
    uint2 hp = make_uint2(
        (uint32_t)__bfloat16_as_ushort(h0) | ((uint32_t)__bfloat16_as_ushort(h1) << 16),
        (uint32_t)__bfloat16_as_ushort(h2) | ((uint32_t)__bfloat16_as_ushort(h3) << 16));
    uint2 lp = make_uint2(
        (uint32_t)__bfloat16_as_ushort(l0) | ((uint32_t)__bfloat16_as_ushort(l1) << 16),
        (uint32_t)__bfloat16_as_ushort(l2) | ((uint32_t)__bfloat16_as_ushort(l3) << 16));
    ((uint2*)d0)[i] = hp;
    ((uint2*)d1)[i] = lp;
}

// ---------------------------------------------------------------------------
// Depthwise 3x3 SAME conv, row-pair stencil. q/k fp32 in-place + fused norms;
// v -> bf16 hi/lo split planes.
// ---------------------------------------------------------------------------
__global__ __launch_bounds__(256)
void dwconv3x3(float* __restrict__ qkv, const float* __restrict__ wdw,
               float* __restrict__ inv,
               __nv_bfloat16* __restrict__ V0, __nv_bfloat16* __restrict__ V1)
{
    const int plane = blockIdx.x;
    const int b     = plane / C3;
    const int ch    = plane % C3;
    float* p = qkv + (size_t)plane * HW;

    __shared__ float s[66][72];
    const int t = threadIdx.x;

    if (t < 72)       { s[0][t] = 0.f; s[65][t] = 0.f; }
    else if (t < 136) { s[t - 72 + 1][3]  = 0.f; }
    else if (t < 200) { s[t - 136 + 1][68] = 0.f; }
#pragma unroll
    for (int it = 0; it < 4; it++) {
        int i = t + it * 256;
        int y = i >> 4, x4 = (i & 15) * 4;
        float4 v = *(const float4*)&p[y * 64 + x4];
        *(float4*)&s[y + 1][x4 + 4] = v;
    }

    float w[9];
#pragma unroll
    for (int j = 0; j < 9; j++) w[j] = wdw[ch * 9 + j];
    __syncthreads();

    const bool isv = (ch >= 2 * C_);
    __nv_bfloat16 *v0 = 0, *v1 = 0;
    if (isv) {
        size_t voff = ((size_t)b * C_ + (ch - 2 * C_)) * HW;
        v0 = V0 + voff; v1 = V1 + voff;
    }

    const int y  = (t >> 3) * 2;
    const int x8 = (t & 7) * 8;

    float v[4][16];
#pragma unroll
    for (int r = 0; r < 4; r++) {
        *(float4*)&v[r][0]  = *(float4*)&s[y + r][x8];
        *(float4*)&v[r][4]  = *(float4*)&s[y + r][x8 + 4];
        *(float4*)&v[r][8]  = *(float4*)&s[y + r][x8 + 8];
        *(float4*)&v[r][12] = *(float4*)&s[y + r][x8 + 12];
    }

    float o[2][8];
#pragma unroll
    for (int rr = 0; rr < 2; rr++)
#pragma unroll
        for (int j = 0; j < 8; j++) {
            float a = 0.f;
#pragma unroll
            for (int dy = 0; dy < 3; dy++)
#pragma unroll
                for (int dx = 0; dx < 3; dx++)
                    a = fmaf(v[rr + dy][3 + j + dx], w[dy * 3 + dx], a);
            o[rr][j] = a;
        }

    float ss = 0.f;
    if (!isv) {
#pragma unroll
        for (int rr = 0; rr < 2; rr++) {
            *(float4*)&p[(y + rr) * 64 + x8]     = make_float4(o[rr][0], o[rr][1], o[rr][2], o[rr][3]);
            *(float4*)&p[(y + rr) * 64 + x8 + 4] = make_float4(o[rr][4], o[rr][5], o[rr][6], o[rr][7]);
#pragma unroll
            for (int j = 0; j < 8; j++) ss = fmaf(o[rr][j], o[rr][j], ss);
        }
    } else {
#pragma unroll
        for (int rr = 0; rr < 2; rr++) {
            uint32_t hp[4], lp[4];
#pragma unroll
            for (int j = 0; j < 4; j++) {
                __nv_bfloat16 ha = __float2bfloat16(o[rr][2 * j]);
                __nv_bfloat16 hb = __float2bfloat16(o[rr][2 * j + 1]);
                __nv_bfloat16 la = __float2bfloat16(o[rr][2 * j] - __bfloat162float(ha));
                __nv_bfloat16 lb = __float2bfloat16(o[rr][2 * j + 1] - __bfloat162float(hb));
                hp[j] = (uint32_t)__bfloat16_as_ushort(ha) |
                        ((uint32_t)__bfloat16_as_ushort(hb) << 16);
                lp[j] = (uint32_t)__bfloat16_as_ushort(la) |
                        ((uint32_t)__bfloat16_as_ushort(lb) << 16);
            }
            *(uint4*)&v0[(y + rr) * 64 + x8] = make_uint4(hp[0], hp[1], hp[2], hp[3]);
            *(uint4*)&v1[(y + rr) * 64 + x8] = make_uint4(lp[0], lp[1], lp[2], lp[3]);
        }
    }

    if (ch < 2 * C_) {
        for (int off = 16; off > 0; off >>= 1)
            ss += __shfl_down_sync(0xffffffffu, ss, off);
        __shared__ float red[8];
        if ((t & 31) == 0) red[t >> 5] = ss;
        __syncthreads();
        if (t == 0) {
            float tot = 0.f;
#pragma unroll
            for (int i = 0; i < 8; i++) tot += red[i];
            inv[b * 2 * C_ + ch] = 1.f / fmaxf(sqrtf(tot), EPSN);
        }
    }
}

// ---------------------------------------------------------------------------
// Attention scores split-K partials — UNNORMALIZED Gram. Row stride 68 floats
// (272 B, multiple of 16) so float4 smem stores are aligned.
// ---------------------------------------------------------------------------
__global__ __launch_bounds__(256)
void attn_scores(const float* __restrict__ qkv)
{
    const int bh    = blockIdx.y;
    const int b     = bh >> 3;
    const int h     = bh & 7;
    const int chunk = blockIdx.x;
    const int t  = threadIdx.x;
    const int tx = t & 15;
    const int ty = t >> 4;

    const float* qbase = qkv + ((size_t)b * C3 + h * DH) * HW;
    const float* kbase = qbase + (size_t)C_ * HW;

    __shared__ float Qs[DH][68];
    __shared__ float Ks[DH][68];

    float acc[3][3];
#pragma unroll
    for (int i = 0; i < 3; i++)
#pragma unroll
        for (int j = 0; j < 3; j++) acc[i][j] = 0.f;

    const int kb = chunk * CHUNK;
    for (int k0 = 0; k0 < CHUNK; k0 += 64) {
        for (int i = t; i < DH * 16; i += 256) {
            int r  = i >> 4;
            int c4 = (i & 15) * 4;
            *(float4*)&Qs[r][c4] = *(const float4*)&qbase[(size_t)r * HW + kb + k0 + c4];
            *(float4*)&Ks[r][c4] = *(const float4*)&kbase[(size_t)r * HW + kb + k0 + c4];
        }
        __syncthreads();

#pragma unroll 16
        for (int kk = 0; kk < 64; kk++) {
            float q0 = Qs[ty     ][kk];
            float q1 = Qs[ty + 16][kk];
            float q2 = Qs[ty + 32][kk];
            float b0 = Ks[tx     ][kk];
            float b1 = Ks[tx + 16][kk];
            float b2 = Ks[tx + 32][kk];
            acc[0][0] = fmaf(q0, b0, acc[0][0]);
            acc[0][1] = fmaf(q0, b1, acc[0][1]);
            acc[0][2] = fmaf(q0, b2, acc[0][2]);
            acc[1][0] = fmaf(q1, b0, acc[1][0]);
            acc[1][1] = fmaf(q1, b1, acc[1][1]);
            acc[1][2] = fmaf(q1, b2, acc[1][2]);
            acc[2][0] = fmaf(q2, b0, acc[2][0]);
            acc[2][1] = fmaf(q2, b1, acc[2][1]);
            acc[2][2] = fmaf(q2, b2, acc[2][2]);
        }
        __syncthreads();
    }

    float* sp = &g_Spart[chunk][bh][0];
#pragma unroll
    for (int i = 0; i < 3; i++)
#pragma unroll
        for (int j = 0; j < 3; j++)
            sp[(ty + 16 * i) * DH + tx + 16 * j] = acc[i][j];
}

// reduce partials, apply rank-1 norm scaling + temperature, row softmax
__global__ __launch_bounds__(64)
void attn_softmax(const float* __restrict__ temp, const float* __restrict__ inv)
{
    const int bh = blockIdx.x;
    const int b  = bh >> 3;
    const int h  = bh & 7;
    const int r  = threadIdx.x;
    if (r >= DH) return;
    const float* ivq = inv + b * 2 * C_ + h * DH;
    const float* ivk = ivq + C_;
    const float rowscale = ivq[r] * temp[h];

    float vals[DH];
#pragma unroll
    for (int c = 0; c < DH; c++) {
        float s = 0.f;
#pragma unroll
        for (int ch = 0; ch < NCH; ch++)
            s += g_Spart[ch][bh][r * DH + c];
        vals[c] = s * rowscale * ivk[c];
    }
    float m = -INFINITY;
#pragma unroll
    for (int c = 0; c < DH; c++) m = fmaxf(m, vals[c]);
    float sum = 0.f;
#pragma unroll
    for (int c = 0; c < DH; c++) {
        vals[c] = expf(vals[c] - m);
        sum += vals[c];
    }
    float is = 1.f / sum;
#pragma unroll
    for (int c = 0; c < DH; c++)
        g_S[bh][r * DH + c] = vals[c] * is;
}

// ---------------------------------------------------------------------------
// W_eff[b] = W_proj @ blockdiag(A_soft[b]) ; split to bf16. grid = B_*NH.
// ---------------------------------------------------------------------------
__global__ __launch_bounds__(256)
void weff_kernel(const float* __restrict__ wp,
                 __nv_bfloat16* __restrict__ e0, __nv_bfloat16* __restrict__ e1)
{
    const int bh = blockIdx.x;
    const int b  = bh >> 3;
    const int h  = bh & 7;
    const int t  = threadIdx.x;

    __shared__ float As[DH][DH + 1];
    for (int i = t; i < DH * DH; i += 256)
        As[i / DH][i % DH] = g_S[bh][i];
    __syncthreads();

    for (int o = t; o < C_; o += 256) {
        float wrow[DH];
#pragma unroll
        for (int d = 0; d < DH; d++) wrow[d] = wp[(size_t)o * C_ + h * DH + d];
#pragma unroll 4
        for (int e = 0; e < DH; e++) {
            float acc = 0.f;
#pragma unroll
            for (int d = 0; d < DH; d++) acc = fmaf(wrow[d], As[d][e], acc);
            size_t idx = ((size_t)b * C_ + o) * C_ + h * DH + e;
            __nv_bfloat16 hi = __float2bfloat16(acc);
            e0[idx] = hi;
            e1[idx] = __float2bfloat16(acc - __bfloat162float(hi));
        }
    }
}

// ---------------------------------------------------------------------------
extern "C" void kernel_launch(void* const* d_in, const int* in_sizes, int n_in,
                              void* d_out, int out_size)
{
    const float* x      = (const float*)d_in[0];
    const float* w_qkv  = (const float*)d_in[1];
    const float* w_dw   = (const float*)d_in[2];
    const float* w_proj = (const float*)d_in[3];
    const float* temp   = (const float*)d_in[4];
    float* out = (float*)d_out;

    float *qkv, *inv;
    __nv_bfloat16 *W0, *W1, *T0, *T1, *We0, *We1;
    cudaGetSymbolAddress((void**)&qkv, g_qkv);
    cudaGetSymbolAddress((void**)&inv, g_inv);
    cudaGetSymbolAddress((void**)&W0, g_W0);
    cudaGetSymbolAddress((void**)&W1, g_W1);
    cudaGetSymbolAddress((void**)&T0, g_T0);
    cudaGetSymbolAddress((void**)&T1, g_T1);
    cudaGetSymbolAddress((void**)&We0, g_We0);
    cudaGetSymbolAddress((void**)&We1, g_We1);

    cudaFuncSetAttribute(gemm_mma, cudaFuncAttributeMaxDynamicSharedMemorySize, GSMEM);

    // 1) split W_qkv ; split x
    wconvert<<<(C3 * C_ + 255) / 256, 256>>>(w_qkv, W0, W1, C3 * C_);
    xsplit<<<(B_ * C_ * HW / 4 + 255) / 256, 256>>>(x, T0, T1, B_ * C_ * HW / 4);
    // 2) qkv = W_qkv @ x
    gemm_mma<<<dim3(C3 / 128, HW / 256, B_), 256, GSMEM>>>(
        W0, W1, 0, T0, T1, qkv, (size_t)C3 * HW);
    // 3) dwconv: q/k fp32 in-place + norms; v -> bf16 split planes
    dwconv3x3<<<B_ * C3, 256>>>(qkv, w_dw, inv, T0, T1);
    // 4) attention scores (unnormalized Gram) + softmax (applies norms)
    attn_scores<<<dim3(NCH, B_ * NH), 256>>>(qkv);
    attn_softmax<<<B_ * NH, 64>>>(temp, inv);
    // 5) W_eff = W_proj . blockdiag(A)
    weff_kernel<<<B_ * NH, 256>>>(w_proj, We0, We1);
    // 6) out = W_eff[b] @ V
    gemm_mma<<<dim3(C_ / 128, HW / 256, B_), 256, GSMEM>>>(
        We0, We1, (size_t)C_ * C_, T0, T1, out, (size_t)C_ * HW);
}